// round 12
// baseline (speedup 1.0000x reference)
#include <cuda_runtime.h>
#include <cuda_fp16.h>
#include <cstdint>

#define NODES 50
#define EPG   400
#define NGRAPH 512
#define NN    (NGRAPH*NODES)   // 25600
#define NE    (NGRAPH*EPG)     // 204800
#define FDIM  512
#define HEADS 8
#define CH    64
#define NA    5
#define GRUH  128
#define GRUI  1024
#define G3    384
#define EMAX  456              // padded per-graph edge capacity (450 used)

// ---------------- scratch (static device globals; no allocation) ----------------
__device__ float g_bufA[NN*FDIM];
__device__ __half g_Ah[NN*FDIM];
__device__ __half g_BW2[FDIM*FDIM];
__device__ __half g_BW3[FDIM*FDIM];
__device__ __half g_BWih[GRUI*G3];
__device__ float g_alpha[NGRAPH*EMAX*HEADS];
__device__ int   g_srcb[NGRAPH*EMAX];
__device__ int   g_offb[NGRAPH*51];
__device__ float g_GI[NGRAPH*NA*G3];
__device__ float g_GHbuf[NGRAPH*G3];
__device__ float g_h0[NGRAPH*GRUH];
__device__ float g_h1[NGRAPH*GRUH];
__device__ float g_gruout[NGRAPH*NA*GRUH];

// ---------------- helpers ----------------
__device__ __forceinline__ uint32_t smem_u32(const void* p) {
    uint32_t a;
    asm("{ .reg .u64 t; cvta.to.shared.u64 t, %1; cvt.u32.u64 %0, t; }" : "=r"(a) : "l"(p));
    return a;
}
__device__ __forceinline__ void cp16(uint32_t sdst, const void* gsrc) {
    asm volatile("cp.async.cg.shared.global [%0], [%1], 16;" :: "r"(sdst), "l"(gsrc) : "memory");
}
__device__ __forceinline__ uint32_t lds32(uint32_t a) {
    uint32_t v;
    asm volatile("ld.shared.b32 %0, [%1];" : "=r"(v) : "r"(a));
    return v;
}
__device__ __forceinline__ void mma16816h(float* c, uint32_t a0, uint32_t a1,
                                          uint32_t a2, uint32_t a3,
                                          uint32_t b0, uint32_t b1) {
    asm volatile(
        "mma.sync.aligned.m16n8k16.row.col.f32.f16.f16.f32 "
        "{%0,%1,%2,%3}, {%4,%5,%6,%7}, {%8,%9}, {%0,%1,%2,%3};"
        : "+f"(c[0]), "+f"(c[1]), "+f"(c[2]), "+f"(c[3])
        : "r"(a0), "r"(a1), "r"(a2), "r"(a3), "r"(b0), "r"(b1));
}

// ---------------- all three weight transpose-converts in one launch --------------
#define NW2 (FDIM*FDIM)
#define NW3 (FDIM*FDIM)
#define NWIH (GRUI*G3)
__global__ void convAll_k(const float* __restrict__ W2, const float* __restrict__ W3,
                          const float* __restrict__ Wih,
                          __half* __restrict__ B2, __half* __restrict__ B3,
                          __half* __restrict__ Bih) {
    int idx = blockIdx.x * 256 + threadIdx.x;
    if (idx < NW2) {
        int n = idx >> 9, k = idx & 511;
        B2[idx] = __float2half_rn(W2[(size_t)k * FDIM + n]);
    } else if (idx < NW2 + NW3) {
        int i = idx - NW2;
        int n = i >> 9, k = i & 511;
        B3[i] = __float2half_rn(W3[(size_t)k * FDIM + n]);
    } else if (idx < NW2 + NW3 + NWIH) {
        int i = idx - NW2 - NW3;
        int n = i / GRUI, k = i - n * GRUI;
        Bih[i] = __float2half_rn(Wih[(size_t)k * G3 + n]);
    }
}

// ---------------- HMMA fp16 GEMM: C[M,N] = A[M,K] * B[N,K]^T ---------------------
#define STAGES 3
#define PITCH 80
#define MAT_BYTES (128*PITCH)
#define STAGE_BYTES (2*MAT_BYTES)        // A | B
#define GEMM_SMEM (STAGES*STAGE_BYTES)   // 61440

__global__ void __launch_bounds__(256) gemm_mma(
    const __half* __restrict__ A, const __half* __restrict__ B,
    float* __restrict__ C, int M, int N, int K) {
    extern __shared__ char sm8[];
    const uint32_t sb = smem_u32(sm8);
    const int tid = threadIdx.x;
    const int lane = tid & 31, wid = tid >> 5;
    const int wm = wid & 3, wn = wid >> 2;
    const int bm = blockIdx.y * 128, bn = blockIdx.x * 128;
    const int g = lane >> 2, tig = lane & 3;
    const int NCH = K >> 5;

    const char* pA = (const char*)A;
    const char* pB = (const char*)B;
    const size_t rowb = (size_t)K * 2;

    auto load_stage = [&](int kc, int s) {
        uint32_t sbase = sb + s * STAGE_BYTES;
        size_t kb = (size_t)kc * 64;
#pragma unroll
        for (int i = tid; i < 512; i += 256) {
            int r = i >> 2, gg = i & 3;
            uint32_t so = sbase + r * PITCH + gg * 16;
            size_t ga = (size_t)(bm + r) * rowb + kb + gg * 16;
            size_t gb = (size_t)(bn + r) * rowb + kb + gg * 16;
            cp16(so,             pA + ga);
            cp16(so + MAT_BYTES, pB + gb);
        }
        asm volatile("cp.async.commit_group;" ::: "memory");
    };

    float acc[2][8][4];
#pragma unroll
    for (int f = 0; f < 2; f++)
#pragma unroll
        for (int nf = 0; nf < 8; nf++)
#pragma unroll
            for (int c = 0; c < 4; c++) acc[f][nf][c] = 0.f;

    load_stage(0, 0);
    load_stage(1, 1);

    for (int kc = 0; kc < NCH; kc++) {
        int s = kc % STAGES;
        asm volatile("cp.async.wait_group 1;" ::: "memory");
        __syncthreads();
        if (kc + 2 < NCH) load_stage(kc + 2, (kc + 2) % STAGES);
        else asm volatile("cp.async.commit_group;" ::: "memory");

        uint32_t aA = sb + s * STAGE_BYTES;
        uint32_t aB = aA + MAT_BYTES;
#pragma unroll
        for (int kk = 0; kk < 2; kk++) {
            const uint32_t kof = kk * 32 + tig * 4;
            uint32_t ah[2][4];
#pragma unroll
            for (int f = 0; f < 2; f++) {
                uint32_t r0 = (uint32_t)(wm * 32 + f * 16 + g) * PITCH + kof;
                ah[f][0] = lds32(aA + r0);
                ah[f][1] = lds32(aA + r0 + 8*PITCH);
                ah[f][2] = lds32(aA + r0 + 16);
                ah[f][3] = lds32(aA + r0 + 8*PITCH + 16);
            }
#pragma unroll
            for (int nf = 0; nf < 8; nf++) {
                uint32_t n0 = (uint32_t)(wn * 64 + nf * 8 + g) * PITCH + kof;
                uint32_t bh0 = lds32(aB + n0);
                uint32_t bh1 = lds32(aB + n0 + 16);
#pragma unroll
                for (int f = 0; f < 2; f++)
                    mma16816h(acc[f][nf], ah[f][0], ah[f][1], ah[f][2], ah[f][3], bh0, bh1);
            }
        }
        __syncthreads();
    }

#pragma unroll
    for (int f = 0; f < 2; f++) {
        int r0 = bm + wm * 32 + f * 16 + g;
#pragma unroll
        for (int nf = 0; nf < 8; nf++) {
            int c0 = bn + wn * 64 + nf * 8 + 2 * tig;
            *(float2*)&C[(size_t)r0 * N + c0]       = make_float2(acc[f][nf][0], acc[f][nf][1]);
            *(float2*)&C[(size_t)(r0 + 8) * N + c0] = make_float2(acc[f][nf][2], acc[f][nf][3]);
        }
    }
}

// ---------------- x @ W1  (K=4) ----------------
__global__ void lin1_k(const float* __restrict__ x, const float* __restrict__ W,
                       float* __restrict__ out) {
    int idx = blockIdx.x * 256 + threadIdx.x;
    int n = idx >> 9, f = idx & 511;
    const float* xr = x + n * 4;
    out[idx] = xr[0]*W[f] + xr[1]*W[512+f] + xr[2]*W[1024+f] + xr[3]*W[1536+f];
}

// ---------------- GAT kernel A: attention (per graph, small smem, hi occ) --------
template <bool LOOPS>
__global__ void __launch_bounds__(256) gat_attn(
    const float* __restrict__ hpre,
    const int* __restrict__ esrc, const int* __restrict__ edst,
    const float* __restrict__ ea,
    const float* __restrict__ a_src, const float* __restrict__ a_dst,
    const float* __restrict__ We, const float* __restrict__ ae,
    float* __restrict__ galpha, int* __restrict__ gsrcb, int* __restrict__ goffb) {
    __shared__ float sh_ssrc[400];
    __shared__ float sh_sdst[400];
    __shared__ float sh_alS[EMAX*8];
    __shared__ float sh_den[400];
    __shared__ float sh_av[1024];
    __shared__ float sh_weae[8];
    __shared__ float sh_easum[52];
    __shared__ int   sh_amaxi[400];
    __shared__ int   sh_srcS[EMAX];
    __shared__ int   sh_dstS[EMAX];
    __shared__ int   sh_cnt[52];
    __shared__ int   sh_off[52];
    __shared__ int   sh_cur[52];

    const int g = blockIdx.x;
    const int nb = g * NODES;
    const int eb = g * EPG;
    const int tid = threadIdx.x;
    const int lane = tid & 31, wid = tid >> 5;
    const int ECNT = LOOPS ? (EPG + NODES) : EPG;

    for (int i = tid; i < 400; i += 256) { sh_den[i] = 0.f; sh_amaxi[i] = 0; }
    if (tid < NODES) { sh_cnt[tid] = 0; sh_easum[tid] = 0.f; sh_cur[tid] = 0; }
    for (int i = tid; i < 512; i += 256) {
        sh_av[i] = a_src[i];
        sh_av[512 + i] = a_dst[i];
    }
    if (tid < 8) {
        float s = 0.f;
#pragma unroll
        for (int c = 0; c < 64; c++) s += We[tid * 64 + c] * ae[tid * 64 + c];
        sh_weae[tid] = s;
    }
    __syncthreads();

    for (int e = tid; e < EPG; e += 256) {
        int d = edst[eb + e] - nb;
        atomicAdd(&sh_cnt[d], 1);
        atomicAdd(&sh_easum[d], ea[eb + e]);
    }
    __syncthreads();

    // per-(node,head) scores: warp per node, h read from global once
    for (int n = wid; n < NODES; n += 8) {
        const float4* hr = (const float4*)(hpre + (size_t)(nb + n) * FDIM);
#pragma unroll
        for (int k = 0; k < 4; k++) {
            float4 v = hr[lane + 32 * k];
            int f = 4 * lane + 128 * k;
            float4 as = *(const float4*)(sh_av + f);
            float4 ad = *(const float4*)(sh_av + 512 + f);
            float s1 = v.x*as.x + v.y*as.y + v.z*as.z + v.w*as.w;
            float s2 = v.x*ad.x + v.y*ad.y + v.z*ad.z + v.w*ad.w;
#pragma unroll
            for (int o = 8; o > 0; o >>= 1) {
                s1 += __shfl_xor_sync(0xffffffffu, s1, o);
                s2 += __shfl_xor_sync(0xffffffffu, s2, o);
            }
            if ((lane & 15) == 0) {
                int head = 2 * k + (lane >> 4);
                sh_ssrc[n * 8 + head] = s1;
                sh_sdst[n * 8 + head] = s2;
            }
        }
    }
    __syncthreads();

    if (tid == 0) {
        int o = 0;
        for (int n = 0; n < NODES; n++) { sh_off[n] = o; o += sh_cnt[n] + (LOOPS ? 1 : 0); }
    }
    __syncthreads();

    for (int e = tid; e < ECNT; e += 256) {
        int sl, dl; float eav;
        if (e < EPG) { sl = esrc[eb + e] - nb; dl = edst[eb + e] - nb; eav = ea[eb + e]; }
        else { sl = dl = e - EPG; eav = sh_easum[dl] / fmaxf((float)sh_cnt[dl], 1.f); }
        int pos = sh_off[dl] + atomicAdd(&sh_cur[dl], 1);
        sh_srcS[pos] = sl; sh_dstS[pos] = dl;
#pragma unroll
        for (int h = 0; h < 8; h++) {
            float al = sh_ssrc[sl * 8 + h] + sh_sdst[dl * 8 + h] + eav * sh_weae[h];
            al = al > 0.f ? al : 0.2f * al;
            sh_alS[pos * 8 + h] = al;
            atomicMax(&sh_amaxi[dl * 8 + h], __float_as_int(al));
        }
    }
    __syncthreads();

    for (int i = tid; i < ECNT; i += 256) {
        int dl = sh_dstS[i];
#pragma unroll
        for (int h = 0; h < 8; h++) {
            float p = expf(sh_alS[i * 8 + h] - __int_as_float(sh_amaxi[dl * 8 + h]));
            sh_alS[i * 8 + h] = p;
            atomicAdd(&sh_den[dl * 8 + h], p);
        }
    }
    __syncthreads();
    for (int i = tid; i < 400; i += 256) sh_den[i] = 1.f / (sh_den[i] + 1e-16f);
    __syncthreads();

    // write normalized alpha + sorted src + offsets to global scratch
    float* ga = galpha + (size_t)g * EMAX * 8;
    int* gs = gsrcb + (size_t)g * EMAX;
    for (int i = tid; i < ECNT; i += 256) {
        int dl = sh_dstS[i];
        float4 o0, o1;
        o0.x = sh_alS[i*8+0] * sh_den[dl*8+0];
        o0.y = sh_alS[i*8+1] * sh_den[dl*8+1];
        o0.z = sh_alS[i*8+2] * sh_den[dl*8+2];
        o0.w = sh_alS[i*8+3] * sh_den[dl*8+3];
        o1.x = sh_alS[i*8+4] * sh_den[dl*8+4];
        o1.y = sh_alS[i*8+5] * sh_den[dl*8+5];
        o1.z = sh_alS[i*8+6] * sh_den[dl*8+6];
        o1.w = sh_alS[i*8+7] * sh_den[dl*8+7];
        ((float4*)(ga + i * 8))[0] = o0;
        ((float4*)(ga + i * 8))[1] = o1;
        gs[i] = sh_srcS[i];
    }
    if (tid < NODES) goffb[g * 51 + tid] = sh_off[tid];
    if (tid == NODES) goffb[g * 51 + NODES] = ECNT;
}

// ---------------- GAT kernel B: aggregation (graph x 128-feature slice) ----------
// writes fp16 (feeds next GEMM A operand)
__global__ void __launch_bounds__(256) gat_aggr(
    const float* __restrict__ hpre,
    const float* __restrict__ galpha, const int* __restrict__ gsrcb,
    const int* __restrict__ goffb,
    const float* __restrict__ bias, __half* __restrict__ outh) {
    __shared__ float sh_hs[NODES * 128];   // 25.6 KB
    __shared__ float sh_al[EMAX * 2];
    __shared__ int   sh_src[EMAX];
    __shared__ int   sh_off[51];

    const int sl = blockIdx.x;     // 0..3
    const int g = blockIdx.y;
    const int nb = g * NODES;
    const int tid = threadIdx.x;
    const int f = tid & 127, half = tid >> 7;
    const int ECNT = goffb[g * 51 + NODES];

    for (int i = tid; i < NODES * 128; i += 256) {
        int n = i >> 7, ff = i & 127;
        sh_hs[i] = hpre[(size_t)(nb + n) * FDIM + sl * 128 + ff];
    }
    const float* ga = galpha + (size_t)g * EMAX * 8 + sl * 2;
    const int* gs = gsrcb + (size_t)g * EMAX;
    for (int i = tid; i < ECNT; i += 256) {
        sh_al[i * 2]     = ga[i * 8];
        sh_al[i * 2 + 1] = ga[i * 8 + 1];
        sh_src[i] = gs[i];
    }
    if (tid <= NODES) sh_off[tid] = goffb[g * 51 + tid];
    __syncthreads();

    const int hsel = f >> 6;
    const float bv = bias[sl * 128 + f];
    for (int n = half; n < NODES; n += 2) {
        float acc = 0.f;
        const int beg = sh_off[n], end = sh_off[n + 1];
        for (int j = beg; j < end; j++)
            acc += sh_al[j * 2 + hsel] * sh_hs[sh_src[j] * 128 + f];
        float v = fmaxf(acc + bv, 0.f);
        outh[(size_t)(nb + n) * FDIM + sl * 128 + f] = __float2half_rn(v);
    }
}

// ---------------- GAT final aggregation: fused pool + agent extraction ------------
// Writes the GRU GEMM operand directly: agent half [0..511] and pooled half [512..1023]
__global__ void __launch_bounds__(256) gat_aggr_final(
    const float* __restrict__ hpre,
    const float* __restrict__ galpha, const int* __restrict__ gsrcb,
    const int* __restrict__ goffb,
    const float* __restrict__ bias, __half* __restrict__ Ah) {
    __shared__ float sh_hs[NODES * 128];
    __shared__ float sh_al[EMAX * 2];
    __shared__ int   sh_src[EMAX];
    __shared__ int   sh_off[51];
    __shared__ float sh_pool[256];

    const int sl = blockIdx.x;     // 0..3
    const int g = blockIdx.y;
    const int nb = g * NODES;
    const int tid = threadIdx.x;
    const int f = tid & 127, half = tid >> 7;
    const int ECNT = goffb[g * 51 + NODES];

    for (int i = tid; i < NODES * 128; i += 256) {
        int n = i >> 7, ff = i & 127;
        sh_hs[i] = hpre[(size_t)(nb + n) * FDIM + sl * 128 + ff];
    }
    const float* ga = galpha + (size_t)g * EMAX * 8 + sl * 2;
    const int* gs = gsrcb + (size_t)g * EMAX;
    for (int i = tid; i < ECNT; i += 256) {
        sh_al[i * 2]     = ga[i * 8];
        sh_al[i * 2 + 1] = ga[i * 8 + 1];
        sh_src[i] = gs[i];
    }
    if (tid <= NODES) sh_off[tid] = goffb[g * 51 + tid];
    __syncthreads();

    const int hsel = f >> 6;
    const float bv = bias[sl * 128 + f];
    float psum = 0.f;
    for (int n = half; n < NODES; n += 2) {
        float acc = 0.f;
        const int beg = sh_off[n], end = sh_off[n + 1];
        for (int j = beg; j < end; j++)
            acc += sh_al[j * 2 + hsel] * sh_hs[sh_src[j] * 128 + f];
        float v = fmaxf(acc + bv, 0.f);
        psum += v;
        if (n < NA)
            Ah[(size_t)(g * NA + n) * GRUI + sl * 128 + f] = __float2half_rn(v);
    }
    sh_pool[tid] = psum;
    __syncthreads();
    if (half == 0) {
        float tot = (sh_pool[tid] + sh_pool[tid + 128]) * (1.f / 50.f);
        __half hv = __float2half_rn(tot);
#pragma unroll
        for (int t = 0; t < NA; t++)
            Ah[(size_t)(g * NA + t) * GRUI + 512 + sl * 128 + f] = hv;
    }
}

// ---------------- GRU: GH = h @ Whh ----------------
__global__ void gru_gh_k(const float* __restrict__ h, const float* __restrict__ Whh,
                         float* __restrict__ GH) {
    __shared__ float hs[8 * GRUH];
    int b0 = blockIdx.x * 8;
    int tid = threadIdx.x;
    for (int i = tid; i < 8 * GRUH; i += 384) hs[i] = h[b0 * GRUH + i];
    __syncthreads();
    float acc[8];
#pragma unroll
    for (int r = 0; r < 8; r++) acc[r] = 0.f;
    for (int k = 0; k < GRUH; k++) {
        float w = Whh[k * G3 + tid];
#pragma unroll
        for (int r = 0; r < 8; r++) acc[r] += hs[r * GRUH + k] * w;
    }
#pragma unroll
    for (int r = 0; r < 8; r++) GH[(b0 + r) * G3 + tid] = acc[r];
}

// ---------------- GRU gate math ----------------
__global__ void gru_gate_k(const float* __restrict__ GI, int t,
                           const float* __restrict__ GHb, const float* __restrict__ hprev,
                           const float* __restrict__ bih, const float* __restrict__ bhh,
                           float* __restrict__ hnew, float* __restrict__ gout,
                           float* __restrict__ hlast) {
    int b = blockIdx.x, j = threadIdx.x;
    const float* gi = GI + (size_t)(b * NA + t) * G3;
    const float* gh = GHb + (size_t)b * G3;
    float ir = gi[j] + bih[j];
    float iz = gi[j + 128] + bih[j + 128];
    float in_ = gi[j + 256] + bih[j + 256];
    float hr = gh[j] + bhh[j];
    float hz = gh[j + 128] + bhh[j + 128];
    float hn = gh[j + 256] + bhh[j + 256];
    float r = 1.f / (1.f + expf(-(ir + hr)));
    float z = 1.f / (1.f + expf(-(iz + hz)));
    float nn = tanhf(in_ + r * hn);
    float hp = hprev[b * GRUH + j];
    float h = (1.f - z) * nn + z * hp;
    hnew[b * GRUH + j] = h;
    gout[(size_t)(b * NA + t) * GRUH + j] = h;
    if (hlast) hlast[b * GRUH + j] = h;
}

// ---------------- FC head ----------------
__global__ void fc_k(const float* __restrict__ gout, const float* __restrict__ W1,
                     const float* __restrict__ b1, const float* __restrict__ W2,
                     const float* __restrict__ b2, const float* __restrict__ ls,
                     float* __restrict__ out) {
    __shared__ float g[128];
    __shared__ float f1[64];
    int r = blockIdx.x, tid = threadIdx.x;
    g[tid] = gout[(size_t)r * GRUH + tid];
    g[tid + 64] = gout[(size_t)r * GRUH + tid + 64];
    __syncthreads();
    float acc = b1[tid];
#pragma unroll 8
    for (int k = 0; k < 128; k++) acc += g[k] * W1[k * 64 + tid];
    f1[tid] = acc > 0.f ? acc : 0.f;
    __syncthreads();
    if (tid < 3) {
        float a2 = b2[tid];
#pragma unroll
        for (int k = 0; k < 64; k++) a2 += f1[k] * W2[k * 3 + tid];
        out[r * 3 + tid] = a2;
        float l = ls[tid];
        l = fminf(fmaxf(l, -20.f), 2.f);
        out[NGRAPH * NA * 3 + r * 3 + tid] = expf(l);
    }
}

// ---------------- launch ----------------
extern "C" void kernel_launch(void* const* d_in, const int* in_sizes, int n_in,
                              void* d_out, int out_size) {
    const float* x      = (const float*)d_in[0];
    const int*   ei     = (const int*)d_in[1];
    const float* ea     = (const float*)d_in[2];
    const float* hid0   = (const float*)d_in[3];
    const float* W1     = (const float*)d_in[4];
    const float* a_s1   = (const float*)d_in[5];
    const float* a_d1   = (const float*)d_in[6];
    const float* We1    = (const float*)d_in[7];
    const float* ae1    = (const float*)d_in[8];
    const float* b1     = (const float*)d_in[9];
    const float* W2     = (const float*)d_in[10];
    const float* a_s2   = (const float*)d_in[11];
    const float* a_d2   = (const float*)d_in[12];
    const float* We2    = (const float*)d_in[13];
    const float* ae2    = (const float*)d_in[14];
    const float* b2     = (const float*)d_in[15];
    const float* W3     = (const float*)d_in[16];
    const float* a_s3   = (const float*)d_in[17];
    const float* a_d3   = (const float*)d_in[18];
    const float* We3    = (const float*)d_in[19];
    const float* ae3    = (const float*)d_in[20];
    const float* b3     = (const float*)d_in[21];
    const float* Wih    = (const float*)d_in[22];
    const float* Whh    = (const float*)d_in[23];
    const float* bih    = (const float*)d_in[24];
    const float* bhh    = (const float*)d_in[25];
    const float* fc1W   = (const float*)d_in[26];
    const float* fc1b   = (const float*)d_in[27];
    const float* fc2W   = (const float*)d_in[28];
    const float* fc2b   = (const float*)d_in[29];
    const float* logstd = (const float*)d_in[30];
    float* out = (float*)d_out;

    float *bufA, *GI, *GHb, *h0b, *h1b, *gout, *alphab;
    int *srcb, *offb;
    __half *Ah, *B2, *B3, *Bih;
    cudaGetSymbolAddress((void**)&bufA, g_bufA);
    cudaGetSymbolAddress((void**)&GI,   g_GI);
    cudaGetSymbolAddress((void**)&GHb,  g_GHbuf);
    cudaGetSymbolAddress((void**)&h0b,  g_h0);
    cudaGetSymbolAddress((void**)&h1b,  g_h1);
    cudaGetSymbolAddress((void**)&gout, g_gruout);
    cudaGetSymbolAddress((void**)&alphab, g_alpha);
    cudaGetSymbolAddress((void**)&srcb, g_srcb);
    cudaGetSymbolAddress((void**)&offb, g_offb);
    cudaGetSymbolAddress((void**)&Ah, g_Ah);
    cudaGetSymbolAddress((void**)&B2, g_BW2);
    cudaGetSymbolAddress((void**)&B3, g_BW3);
    cudaGetSymbolAddress((void**)&Bih, g_BWih);

    cudaFuncSetAttribute((const void*)gemm_mma,
                         cudaFuncAttributeMaxDynamicSharedMemorySize, GEMM_SMEM);

    const int* esrc = ei;
    const int* edst = ei + NE;

    // all weight conversions up front, one launch
    convAll_k<<<(NW2 + NW3 + NWIH + 255) / 256, 256>>>(W2, W3, Wih, B2, B3, Bih);
    // layer 1 -> fp16 A operand directly
    lin1_k<<<(NN * FDIM) / 256, 256>>>(x, W1, bufA);
    gat_attn<false><<<NGRAPH, 256>>>(bufA, esrc, edst, ea, a_s1, a_d1, We1, ae1,
                                     alphab, srcb, offb);
    gat_aggr<<<dim3(4, NGRAPH), 256>>>(bufA, alphab, srcb, offb, b1, Ah);
    // layer 2
    gemm_mma<<<dim3(FDIM / 128, NN / 128), 256, GEMM_SMEM>>>(Ah, B2, bufA,
                                                             NN, FDIM, FDIM);
    gat_attn<true><<<NGRAPH, 256>>>(bufA, esrc, edst, ea, a_s2, a_d2, We2, ae2,
                                    alphab, srcb, offb);
    gat_aggr<<<dim3(4, NGRAPH), 256>>>(bufA, alphab, srcb, offb, b2, Ah);
    // layer 3 -> fused pool + agent -> GRU GEMM operand
    gemm_mma<<<dim3(FDIM / 128, NN / 128), 256, GEMM_SMEM>>>(Ah, B3, bufA,
                                                             NN, FDIM, FDIM);
    gat_attn<true><<<NGRAPH, 256>>>(bufA, esrc, edst, ea, a_s3, a_d3, We3, ae3,
                                    alphab, srcb, offb);
    gat_aggr_final<<<dim3(4, NGRAPH), 256>>>(bufA, alphab, srcb, offb, b3, Ah);
    // GI GEMM
    gemm_mma<<<dim3(G3 / 128, (NGRAPH * NA) / 128), 256, GEMM_SMEM>>>(
        Ah, Bih, GI, NGRAPH * NA, G3, GRUI);
    // GRU recurrence (10-launch — frozen)
    cudaMemcpyAsync(h0b, hid0, (size_t)NGRAPH * GRUH * sizeof(float),
                    cudaMemcpyDeviceToDevice);
    for (int t = 0; t < NA; t++) {
        float* hc = (t & 1) ? h1b : h0b;
        float* hn = (t & 1) ? h0b : h1b;
        gru_gh_k<<<NGRAPH / 8, G3>>>(hc, Whh, GHb);
        gru_gate_k<<<NGRAPH, GRUH>>>(GI, t, GHb, hc, bih, bhh, hn, gout,
                                     (t == NA - 1) ? (out + NGRAPH * NA * 3 * 2) : nullptr);
    }
    fc_k<<<NGRAPH * NA, 64>>>(gout, fc1W, fc1b, fc2W, fc2b, logstd, out);
}

// round 13
// speedup vs baseline: 1.7157x; 1.7157x over previous
#include <cuda_runtime.h>
#include <cuda_fp16.h>
#include <cstdint>

#define NODES 50
#define EPG   400
#define NGRAPH 512
#define NN    (NGRAPH*NODES)   // 25600
#define NE    (NGRAPH*EPG)     // 204800
#define FDIM  512
#define HEADS 8
#define CH    64
#define NA    5
#define GRUH  128
#define GRUI  1024
#define G3    384
#define EMAX  456              // padded per-graph edge capacity (450 used)

// ---------------- scratch (static device globals; no allocation) ----------------
__device__ float g_bufA[NN*FDIM];
__device__ float g_bufB[NN*FDIM];
__device__ __half g_Ah[NN*FDIM];
__device__ __half g_Bh[GRUI*G3 > FDIM*FDIM ? GRUI*G3 : FDIM*FDIM];
__device__ float g_alpha[NGRAPH*EMAX*HEADS];
__device__ int   g_srcb[NGRAPH*EMAX];
__device__ int   g_offb[NGRAPH*51];
__device__ float g_GI[NGRAPH*NA*G3];
__device__ float g_GHbuf[NGRAPH*G3];
__device__ float g_h0[NGRAPH*GRUH];
__device__ float g_h1[NGRAPH*GRUH];
__device__ float g_gruout[NGRAPH*NA*GRUH];

// ---------------- helpers ----------------
__device__ __forceinline__ uint32_t smem_u32(const void* p) {
    uint32_t a;
    asm("{ .reg .u64 t; cvta.to.shared.u64 t, %1; cvt.u32.u64 %0, t; }" : "=r"(a) : "l"(p));
    return a;
}
__device__ __forceinline__ void cp16(uint32_t sdst, const void* gsrc) {
    asm volatile("cp.async.cg.shared.global [%0], [%1], 16;" :: "r"(sdst), "l"(gsrc) : "memory");
}
__device__ __forceinline__ uint32_t lds32(uint32_t a) {
    uint32_t v;
    asm volatile("ld.shared.b32 %0, [%1];" : "=r"(v) : "r"(a));
    return v;
}
__device__ __forceinline__ void mma16816h(float* c, uint32_t a0, uint32_t a1,
                                          uint32_t a2, uint32_t a3,
                                          uint32_t b0, uint32_t b1) {
    asm volatile(
        "mma.sync.aligned.m16n8k16.row.col.f32.f16.f16.f32 "
        "{%0,%1,%2,%3}, {%4,%5,%6,%7}, {%8,%9}, {%0,%1,%2,%3};"
        : "+f"(c[0]), "+f"(c[1]), "+f"(c[2]), "+f"(c[3])
        : "r"(a0), "r"(a1), "r"(a2), "r"(a3), "r"(b0), "r"(b1));
}

// W [K,N] fp32 -> Wt [N,K] fp16 (transposed convert)
__global__ void convT_k(const float* __restrict__ W, __half* __restrict__ hi,
                        int K, int N) {
    int idx = blockIdx.x * 256 + threadIdx.x;
    if (idx >= N * K) return;
    int n = idx / K, k = idx - n * K;
    hi[idx] = __float2half_rn(W[(size_t)k * N + n]);
}

// ---------------- HMMA fp16 GEMM: C[M,N] = A[M,K] * B[N,K]^T ---------------------
#define STAGES 3
#define PITCH 80
#define MAT_BYTES (128*PITCH)
#define STAGE_BYTES (2*MAT_BYTES)        // A | B
#define GEMM_SMEM (STAGES*STAGE_BYTES)   // 61440

__global__ void __launch_bounds__(256) gemm_mma(
    const __half* __restrict__ A, const __half* __restrict__ B,
    float* __restrict__ C, int M, int N, int K) {
    extern __shared__ char sm8[];
    const uint32_t sb = smem_u32(sm8);
    const int tid = threadIdx.x;
    const int lane = tid & 31, wid = tid >> 5;
    const int wm = wid & 3, wn = wid >> 2;
    const int bm = blockIdx.y * 128, bn = blockIdx.x * 128;
    const int g = lane >> 2, tig = lane & 3;
    const int NCH = K >> 5;

    const char* pA = (const char*)A;
    const char* pB = (const char*)B;
    const size_t rowb = (size_t)K * 2;

    auto load_stage = [&](int kc, int s) {
        uint32_t sbase = sb + s * STAGE_BYTES;
        size_t kb = (size_t)kc * 64;
#pragma unroll
        for (int i = tid; i < 512; i += 256) {
            int r = i >> 2, gg = i & 3;
            uint32_t so = sbase + r * PITCH + gg * 16;
            size_t ga = (size_t)(bm + r) * rowb + kb + gg * 16;
            size_t gb = (size_t)(bn + r) * rowb + kb + gg * 16;
            cp16(so,             pA + ga);
            cp16(so + MAT_BYTES, pB + gb);
        }
        asm volatile("cp.async.commit_group;" ::: "memory");
    };

    float acc[2][8][4];
#pragma unroll
    for (int f = 0; f < 2; f++)
#pragma unroll
        for (int nf = 0; nf < 8; nf++)
#pragma unroll
            for (int c = 0; c < 4; c++) acc[f][nf][c] = 0.f;

    load_stage(0, 0);
    load_stage(1, 1);

    for (int kc = 0; kc < NCH; kc++) {
        int s = kc % STAGES;
        asm volatile("cp.async.wait_group 1;" ::: "memory");
        __syncthreads();
        if (kc + 2 < NCH) load_stage(kc + 2, (kc + 2) % STAGES);
        else asm volatile("cp.async.commit_group;" ::: "memory");

        uint32_t aA = sb + s * STAGE_BYTES;
        uint32_t aB = aA + MAT_BYTES;
#pragma unroll
        for (int kk = 0; kk < 2; kk++) {
            const uint32_t kof = kk * 32 + tig * 4;
            uint32_t ah[2][4];
#pragma unroll
            for (int f = 0; f < 2; f++) {
                uint32_t r0 = (uint32_t)(wm * 32 + f * 16 + g) * PITCH + kof;
                ah[f][0] = lds32(aA + r0);
                ah[f][1] = lds32(aA + r0 + 8*PITCH);
                ah[f][2] = lds32(aA + r0 + 16);
                ah[f][3] = lds32(aA + r0 + 8*PITCH + 16);
            }
#pragma unroll
            for (int nf = 0; nf < 8; nf++) {
                uint32_t n0 = (uint32_t)(wn * 64 + nf * 8 + g) * PITCH + kof;
                uint32_t bh0 = lds32(aB + n0);
                uint32_t bh1 = lds32(aB + n0 + 16);
#pragma unroll
                for (int f = 0; f < 2; f++)
                    mma16816h(acc[f][nf], ah[f][0], ah[f][1], ah[f][2], ah[f][3], bh0, bh1);
            }
        }
        __syncthreads();
    }

#pragma unroll
    for (int f = 0; f < 2; f++) {
        int r0 = bm + wm * 32 + f * 16 + g;
#pragma unroll
        for (int nf = 0; nf < 8; nf++) {
            int c0 = bn + wn * 64 + nf * 8 + 2 * tig;
            *(float2*)&C[(size_t)r0 * N + c0]       = make_float2(acc[f][nf][0], acc[f][nf][1]);
            *(float2*)&C[(size_t)(r0 + 8) * N + c0] = make_float2(acc[f][nf][2], acc[f][nf][3]);
        }
    }
}

// ---------------- x @ W1  (K=4) ----------------
__global__ void lin1_k(const float* __restrict__ x, const float* __restrict__ W,
                       float* __restrict__ out) {
    int idx = blockIdx.x * 256 + threadIdx.x;
    int n = idx >> 9, f = idx & 511;
    const float* xr = x + n * 4;
    out[idx] = xr[0]*W[f] + xr[1]*W[512+f] + xr[2]*W[1024+f] + xr[3]*W[1536+f];
}

// ---------------- GAT kernel A: attention (per graph, small smem, hi occ) --------
template <bool LOOPS>
__global__ void __launch_bounds__(256) gat_attn(
    const float* __restrict__ hpre,
    const int* __restrict__ esrc, const int* __restrict__ edst,
    const float* __restrict__ ea,
    const float* __restrict__ a_src, const float* __restrict__ a_dst,
    const float* __restrict__ We, const float* __restrict__ ae,
    float* __restrict__ galpha, int* __restrict__ gsrcb, int* __restrict__ goffb) {
    __shared__ float sh_ssrc[400];
    __shared__ float sh_sdst[400];
    __shared__ float sh_alS[EMAX*8];
    __shared__ float sh_den[400];
    __shared__ float sh_av[1024];
    __shared__ float sh_weae[8];
    __shared__ float sh_easum[52];
    __shared__ int   sh_amaxi[400];
    __shared__ int   sh_srcS[EMAX];
    __shared__ int   sh_dstS[EMAX];
    __shared__ int   sh_cnt[52];
    __shared__ int   sh_off[52];
    __shared__ int   sh_cur[52];

    const int g = blockIdx.x;
    const int nb = g * NODES;
    const int eb = g * EPG;
    const int tid = threadIdx.x;
    const int lane = tid & 31, wid = tid >> 5;
    const int ECNT = LOOPS ? (EPG + NODES) : EPG;

    for (int i = tid; i < 400; i += 256) { sh_den[i] = 0.f; sh_amaxi[i] = 0; }
    if (tid < NODES) { sh_cnt[tid] = 0; sh_easum[tid] = 0.f; sh_cur[tid] = 0; }
    for (int i = tid; i < 512; i += 256) {
        sh_av[i] = a_src[i];
        sh_av[512 + i] = a_dst[i];
    }
    if (tid < 8) {
        float s = 0.f;
#pragma unroll
        for (int c = 0; c < 64; c++) s += We[tid * 64 + c] * ae[tid * 64 + c];
        sh_weae[tid] = s;
    }
    __syncthreads();

    for (int e = tid; e < EPG; e += 256) {
        int d = edst[eb + e] - nb;
        atomicAdd(&sh_cnt[d], 1);
        atomicAdd(&sh_easum[d], ea[eb + e]);
    }
    __syncthreads();

    // per-(node,head) scores: warp per node, h read from global once
    for (int n = wid; n < NODES; n += 8) {
        const float4* hr = (const float4*)(hpre + (size_t)(nb + n) * FDIM);
#pragma unroll
        for (int k = 0; k < 4; k++) {
            float4 v = hr[lane + 32 * k];
            int f = 4 * lane + 128 * k;
            float4 as = *(const float4*)(sh_av + f);
            float4 ad = *(const float4*)(sh_av + 512 + f);
            float s1 = v.x*as.x + v.y*as.y + v.z*as.z + v.w*as.w;
            float s2 = v.x*ad.x + v.y*ad.y + v.z*ad.z + v.w*ad.w;
#pragma unroll
            for (int o = 8; o > 0; o >>= 1) {
                s1 += __shfl_xor_sync(0xffffffffu, s1, o);
                s2 += __shfl_xor_sync(0xffffffffu, s2, o);
            }
            if ((lane & 15) == 0) {
                int head = 2 * k + (lane >> 4);
                sh_ssrc[n * 8 + head] = s1;
                sh_sdst[n * 8 + head] = s2;
            }
        }
    }
    __syncthreads();

    if (tid == 0) {
        int o = 0;
        for (int n = 0; n < NODES; n++) { sh_off[n] = o; o += sh_cnt[n] + (LOOPS ? 1 : 0); }
    }
    __syncthreads();

    for (int e = tid; e < ECNT; e += 256) {
        int sl, dl; float eav;
        if (e < EPG) { sl = esrc[eb + e] - nb; dl = edst[eb + e] - nb; eav = ea[eb + e]; }
        else { sl = dl = e - EPG; eav = sh_easum[dl] / fmaxf((float)sh_cnt[dl], 1.f); }
        int pos = sh_off[dl] + atomicAdd(&sh_cur[dl], 1);
        sh_srcS[pos] = sl; sh_dstS[pos] = dl;
#pragma unroll
        for (int h = 0; h < 8; h++) {
            float al = sh_ssrc[sl * 8 + h] + sh_sdst[dl * 8 + h] + eav * sh_weae[h];
            al = al > 0.f ? al : 0.2f * al;
            sh_alS[pos * 8 + h] = al;
            atomicMax(&sh_amaxi[dl * 8 + h], __float_as_int(al));
        }
    }
    __syncthreads();

    for (int i = tid; i < ECNT; i += 256) {
        int dl = sh_dstS[i];
#pragma unroll
        for (int h = 0; h < 8; h++) {
            float p = expf(sh_alS[i * 8 + h] - __int_as_float(sh_amaxi[dl * 8 + h]));
            sh_alS[i * 8 + h] = p;
            atomicAdd(&sh_den[dl * 8 + h], p);
        }
    }
    __syncthreads();
    for (int i = tid; i < 400; i += 256) sh_den[i] = 1.f / (sh_den[i] + 1e-16f);
    __syncthreads();

    // write normalized alpha + sorted src + offsets to global scratch
    float* ga = galpha + (size_t)g * EMAX * 8;
    int* gs = gsrcb + (size_t)g * EMAX;
    for (int i = tid; i < ECNT; i += 256) {
        int dl = sh_dstS[i];
        float4 o0, o1;
        o0.x = sh_alS[i*8+0] * sh_den[dl*8+0];
        o0.y = sh_alS[i*8+1] * sh_den[dl*8+1];
        o0.z = sh_alS[i*8+2] * sh_den[dl*8+2];
        o0.w = sh_alS[i*8+3] * sh_den[dl*8+3];
        o1.x = sh_alS[i*8+4] * sh_den[dl*8+4];
        o1.y = sh_alS[i*8+5] * sh_den[dl*8+5];
        o1.z = sh_alS[i*8+6] * sh_den[dl*8+6];
        o1.w = sh_alS[i*8+7] * sh_den[dl*8+7];
        ((float4*)(ga + i * 8))[0] = o0;
        ((float4*)(ga + i * 8))[1] = o1;
        gs[i] = sh_srcS[i];
    }
    if (tid < NODES) goffb[g * 51 + tid] = sh_off[tid];
    if (tid == NODES) goffb[g * 51 + NODES] = ECNT;
}

// ---------------- GAT kernel B: aggregation (graph x 128-feature slice) ----------
// Vectorized x4: lane covers 4 consecutive features, warp covers all 128 of slice.
// OUTFP16: write single fp16 (feeds next GEMM A operand) instead of fp32
template <bool OUTFP16>
__global__ void __launch_bounds__(256) gat_aggr(
    const float* __restrict__ hpre,
    const float* __restrict__ galpha, const int* __restrict__ gsrcb,
    const int* __restrict__ goffb,
    const float* __restrict__ bias, float* __restrict__ xout,
    __half* __restrict__ outh) {
    __shared__ float sh_hs[NODES * 128];   // 25.6 KB
    __shared__ float sh_al[EMAX * 2];
    __shared__ int   sh_src[EMAX];
    __shared__ int   sh_off[51];

    const int sl = blockIdx.x;     // 0..3
    const int g = blockIdx.y;
    const int nb = g * NODES;
    const int tid = threadIdx.x;
    const int lane = tid & 31, wg = tid >> 5;
    const int ECNT = goffb[g * 51 + NODES];

    for (int i = tid; i < NODES * 128; i += 256) {
        int n = i >> 7, ff = i & 127;
        sh_hs[i] = hpre[(size_t)(nb + n) * FDIM + sl * 128 + ff];
    }
    const float* ga = galpha + (size_t)g * EMAX * 8 + sl * 2;
    const int* gs = gsrcb + (size_t)g * EMAX;
    for (int i = tid; i < ECNT; i += 256) {
        sh_al[i * 2]     = ga[i * 8];
        sh_al[i * 2 + 1] = ga[i * 8 + 1];
        sh_src[i] = gs[i];
    }
    if (tid <= NODES) sh_off[tid] = goffb[g * 51 + tid];
    __syncthreads();

    const int hsel = lane >> 4;          // features lane*4.. share one head-half
    const int f0 = lane * 4;
    const float4 bv = *(const float4*)(bias + sl * 128 + f0);
    for (int n = wg; n < NODES; n += 8) {
        float4 acc = {0.f, 0.f, 0.f, 0.f};
        const int beg = sh_off[n], end = sh_off[n + 1];
        for (int j = beg; j < end; j++) {
            const int s = sh_src[j];
            const float a = sh_al[j * 2 + hsel];
            const float4 h = *(const float4*)(sh_hs + s * 128 + f0);
            acc.x += a * h.x; acc.y += a * h.y;
            acc.z += a * h.z; acc.w += a * h.w;
        }
        float4 v;
        v.x = fmaxf(acc.x + bv.x, 0.f);
        v.y = fmaxf(acc.y + bv.y, 0.f);
        v.z = fmaxf(acc.z + bv.z, 0.f);
        v.w = fmaxf(acc.w + bv.w, 0.f);
        size_t idx = (size_t)(nb + n) * FDIM + sl * 128 + f0;
        if (OUTFP16) {
            __half2* op = (__half2*)(outh + idx);
            op[0] = __floats2half2_rn(v.x, v.y);
            op[1] = __floats2half2_rn(v.z, v.w);
        } else {
            *(float4*)(xout + idx) = v;
        }
    }
}

// ---------------- mean pool -> fp16 graph-emb half of GRU operand ----------------
__global__ void pool_k(const float* __restrict__ x3, __half* __restrict__ Ah) {
    int b = blockIdx.x;
    int f = blockIdx.y * 128 + threadIdx.x;
    float s = 0.f;
#pragma unroll 10
    for (int n = 0; n < NODES; n++) s += x3[(size_t)(b * NODES + n) * FDIM + f];
    s *= (1.f / 50.f);
    __half h = __float2half_rn(s);
#pragma unroll
    for (int t = 0; t < NA; t++)
        Ah[(size_t)(b * NA + t) * GRUI + 512 + f] = h;
}

// ---------------- agent rows -> fp16 agent half of GRU operand -------------------
__global__ void agent_k(const float* __restrict__ x3, __half* __restrict__ Ah) {
    int r = blockIdx.x;           // b*5 + t
    int b = r / 5, t = r - b * 5;
    for (int f = threadIdx.x; f < 512; f += 128)
        Ah[(size_t)r * GRUI + f] =
            __float2half_rn(x3[(size_t)(b * NODES + t) * FDIM + f]);
}

// ---------------- GRU: GH = h @ Whh ----------------
__global__ void gru_gh_k(const float* __restrict__ h, const float* __restrict__ Whh,
                         float* __restrict__ GH) {
    __shared__ float hs[8 * GRUH];
    int b0 = blockIdx.x * 8;
    int tid = threadIdx.x;
    for (int i = tid; i < 8 * GRUH; i += 384) hs[i] = h[b0 * GRUH + i];
    __syncthreads();
    float acc[8];
#pragma unroll
    for (int r = 0; r < 8; r++) acc[r] = 0.f;
    for (int k = 0; k < GRUH; k++) {
        float w = Whh[k * G3 + tid];
#pragma unroll
        for (int r = 0; r < 8; r++) acc[r] += hs[r * GRUH + k] * w;
    }
#pragma unroll
    for (int r = 0; r < 8; r++) GH[(b0 + r) * G3 + tid] = acc[r];
}

// ---------------- GRU gate math ----------------
__global__ void gru_gate_k(const float* __restrict__ GI, int t,
                           const float* __restrict__ GHb, const float* __restrict__ hprev,
                           const float* __restrict__ bih, const float* __restrict__ bhh,
                           float* __restrict__ hnew, float* __restrict__ gout,
                           float* __restrict__ hlast) {
    int b = blockIdx.x, j = threadIdx.x;
    const float* gi = GI + (size_t)(b * NA + t) * G3;
    const float* gh = GHb + (size_t)b * G3;
    float ir = gi[j] + bih[j];
    float iz = gi[j + 128] + bih[j + 128];
    float in_ = gi[j + 256] + bih[j + 256];
    float hr = gh[j] + bhh[j];
    float hz = gh[j + 128] + bhh[j + 128];
    float hn = gh[j + 256] + bhh[j + 256];
    float r = 1.f / (1.f + expf(-(ir + hr)));
    float z = 1.f / (1.f + expf(-(iz + hz)));
    float nn = tanhf(in_ + r * hn);
    float hp = hprev[b * GRUH + j];
    float h = (1.f - z) * nn + z * hp;
    hnew[b * GRUH + j] = h;
    gout[(size_t)(b * NA + t) * GRUH + j] = h;
    if (hlast) hlast[b * GRUH + j] = h;
}

// ---------------- FC head ----------------
__global__ void fc_k(const float* __restrict__ gout, const float* __restrict__ W1,
                     const float* __restrict__ b1, const float* __restrict__ W2,
                     const float* __restrict__ b2, const float* __restrict__ ls,
                     float* __restrict__ out) {
    __shared__ float g[128];
    __shared__ float f1[64];
    int r = blockIdx.x, tid = threadIdx.x;
    g[tid] = gout[(size_t)r * GRUH + tid];
    g[tid + 64] = gout[(size_t)r * GRUH + tid + 64];
    __syncthreads();
    float acc = b1[tid];
#pragma unroll 8
    for (int k = 0; k < 128; k++) acc += g[k] * W1[k * 64 + tid];
    f1[tid] = acc > 0.f ? acc : 0.f;
    __syncthreads();
    if (tid < 3) {
        float a2 = b2[tid];
#pragma unroll
        for (int k = 0; k < 64; k++) a2 += f1[k] * W2[k * 3 + tid];
        out[r * 3 + tid] = a2;
        float l = ls[tid];
        l = fminf(fmaxf(l, -20.f), 2.f);
        out[NGRAPH * NA * 3 + r * 3 + tid] = expf(l);
    }
}

// ---------------- launch ----------------
extern "C" void kernel_launch(void* const* d_in, const int* in_sizes, int n_in,
                              void* d_out, int out_size) {
    const float* x      = (const float*)d_in[0];
    const int*   ei     = (const int*)d_in[1];
    const float* ea     = (const float*)d_in[2];
    const float* hid0   = (const float*)d_in[3];
    const float* W1     = (const float*)d_in[4];
    const float* a_s1   = (const float*)d_in[5];
    const float* a_d1   = (const float*)d_in[6];
    const float* We1    = (const float*)d_in[7];
    const float* ae1    = (const float*)d_in[8];
    const float* b1     = (const float*)d_in[9];
    const float* W2     = (const float*)d_in[10];
    const float* a_s2   = (const float*)d_in[11];
    const float* a_d2   = (const float*)d_in[12];
    const float* We2    = (const float*)d_in[13];
    const float* ae2    = (const float*)d_in[14];
    const float* b2     = (const float*)d_in[15];
    const float* W3     = (const float*)d_in[16];
    const float* a_s3   = (const float*)d_in[17];
    const float* a_d3   = (const float*)d_in[18];
    const float* We3    = (const float*)d_in[19];
    const float* ae3    = (const float*)d_in[20];
    const float* b3     = (const float*)d_in[21];
    const float* Wih    = (const float*)d_in[22];
    const float* Whh    = (const float*)d_in[23];
    const float* bih    = (const float*)d_in[24];
    const float* bhh    = (const float*)d_in[25];
    const float* fc1W   = (const float*)d_in[26];
    const float* fc1b   = (const float*)d_in[27];
    const float* fc2W   = (const float*)d_in[28];
    const float* fc2b   = (const float*)d_in[29];
    const float* logstd = (const float*)d_in[30];
    float* out = (float*)d_out;

    float *bufA, *bufB, *GI, *GHb, *h0b, *h1b, *gout, *alphab;
    int *srcb, *offb;
    __half *Ah, *Bh;
    cudaGetSymbolAddress((void**)&bufA, g_bufA);
    cudaGetSymbolAddress((void**)&bufB, g_bufB);
    cudaGetSymbolAddress((void**)&GI,   g_GI);
    cudaGetSymbolAddress((void**)&GHb,  g_GHbuf);
    cudaGetSymbolAddress((void**)&h0b,  g_h0);
    cudaGetSymbolAddress((void**)&h1b,  g_h1);
    cudaGetSymbolAddress((void**)&gout, g_gruout);
    cudaGetSymbolAddress((void**)&alphab, g_alpha);
    cudaGetSymbolAddress((void**)&srcb, g_srcb);
    cudaGetSymbolAddress((void**)&offb, g_offb);
    cudaGetSymbolAddress((void**)&Ah, g_Ah);
    cudaGetSymbolAddress((void**)&Bh, g_Bh);

    cudaFuncSetAttribute((const void*)gemm_mma,
                         cudaFuncAttributeMaxDynamicSharedMemorySize, GEMM_SMEM);

    const int* esrc = ei;
    const int* edst = ei + NE;

    // layer 1 -> fp16 A operand directly
    lin1_k<<<(NN * FDIM) / 256, 256>>>(x, W1, bufA);
    gat_attn<false><<<NGRAPH, 256>>>(bufA, esrc, edst, ea, a_s1, a_d1, We1, ae1,
                                     alphab, srcb, offb);
    gat_aggr<true><<<dim3(4, NGRAPH), 256>>>(bufA, alphab, srcb, offb, b1,
                                             nullptr, Ah);
    // layer 2
    convT_k<<<(FDIM * FDIM + 255) / 256, 256>>>(W2, Bh, FDIM, FDIM);
    gemm_mma<<<dim3(FDIM / 128, NN / 128), 256, GEMM_SMEM>>>(Ah, Bh, bufA,
                                                             NN, FDIM, FDIM);
    gat_attn<true><<<NGRAPH, 256>>>(bufA, esrc, edst, ea, a_s2, a_d2, We2, ae2,
                                    alphab, srcb, offb);
    gat_aggr<true><<<dim3(4, NGRAPH), 256>>>(bufA, alphab, srcb, offb, b2,
                                             nullptr, Ah);
    // layer 3 -> fp32 (feeds pool/agent)
    convT_k<<<(FDIM * FDIM + 255) / 256, 256>>>(W3, Bh, FDIM, FDIM);
    gemm_mma<<<dim3(FDIM / 128, NN / 128), 256, GEMM_SMEM>>>(Ah, Bh, bufA,
                                                             NN, FDIM, FDIM);
    gat_attn<true><<<NGRAPH, 256>>>(bufA, esrc, edst, ea, a_s3, a_d3, We3, ae3,
                                    alphab, srcb, offb);
    gat_aggr<false><<<dim3(4, NGRAPH), 256>>>(bufA, alphab, srcb, offb, b3,
                                              bufB, nullptr);
    // pooling + agent rows -> GRU GEMM A operand (fp16), then GI GEMM
    pool_k<<<dim3(NGRAPH, FDIM / 128), 128>>>(bufB, Ah);
    agent_k<<<NGRAPH * NA, 128>>>(bufB, Ah);
    convT_k<<<(GRUI * G3 + 255) / 256, 256>>>(Wih, Bh, GRUI, G3);
    gemm_mma<<<dim3(G3 / 128, (NGRAPH * NA) / 128), 256, GEMM_SMEM>>>(
        Ah, Bh, GI, NGRAPH * NA, G3, GRUI);
    // GRU recurrence (10-launch — frozen)
    cudaMemcpyAsync(h0b, hid0, (size_t)NGRAPH * GRUH * sizeof(float),
                    cudaMemcpyDeviceToDevice);
    for (int t = 0; t < NA; t++) {
        float* hc = (t & 1) ? h1b : h0b;
        float* hn = (t & 1) ? h0b : h1b;
        gru_gh_k<<<NGRAPH / 8, G3>>>(hc, Whh, GHb);
        gru_gate_k<<<NGRAPH, GRUH>>>(GI, t, GHb, hc, bih, bhh, hn, gout,
                                     (t == NA - 1) ? (out + NGRAPH * NA * 3 * 2) : nullptr);
    }
    fc_k<<<NGRAPH * NA, 64>>>(gout, fc1W, fc1b, fc2W, fc2b, logstd, out);
}

// round 14
// speedup vs baseline: 1.8804x; 1.0960x over previous
#include <cuda_runtime.h>
#include <cuda_fp16.h>
#include <cstdint>

#define NODES 50
#define EPG   400
#define NGRAPH 512
#define NN    (NGRAPH*NODES)   // 25600
#define NE    (NGRAPH*EPG)     // 204800
#define FDIM  512
#define HEADS 8
#define CH    64
#define NA    5
#define GRUH  128
#define GRUI  1024
#define G3    384
#define EMAX  456              // padded per-graph edge capacity (450 used)

// ---------------- scratch (static device globals; no allocation) ----------------
__device__ float g_bufA[NN*FDIM];
__device__ float g_bufB[NN*FDIM];
__device__ __half g_Ah[NN*FDIM];
__device__ __half g_Bh[GRUI*G3 > FDIM*FDIM ? GRUI*G3 : FDIM*FDIM];
__device__ float g_alpha[NGRAPH*EMAX*HEADS];
__device__ int   g_srcb[NGRAPH*EMAX];
__device__ int   g_offb[NGRAPH*51];
__device__ float g_GI[NGRAPH*NA*G3];
__device__ float g_GHbuf[NGRAPH*G3];
__device__ float g_h0[NGRAPH*GRUH];
__device__ float g_h1[NGRAPH*GRUH];
__device__ float g_gruout[NGRAPH*NA*GRUH];

// ---------------- helpers ----------------
__device__ __forceinline__ uint32_t smem_u32(const void* p) {
    uint32_t a;
    asm("{ .reg .u64 t; cvta.to.shared.u64 t, %1; cvt.u32.u64 %0, t; }" : "=r"(a) : "l"(p));
    return a;
}
__device__ __forceinline__ void cp16(uint32_t sdst, const void* gsrc) {
    asm volatile("cp.async.cg.shared.global [%0], [%1], 16;" :: "r"(sdst), "l"(gsrc) : "memory");
}
__device__ __forceinline__ uint32_t lds32(uint32_t a) {
    uint32_t v;
    asm volatile("ld.shared.b32 %0, [%1];" : "=r"(v) : "r"(a));
    return v;
}
__device__ __forceinline__ void mma16816h(float* c, uint32_t a0, uint32_t a1,
                                          uint32_t a2, uint32_t a3,
                                          uint32_t b0, uint32_t b1) {
    asm volatile(
        "mma.sync.aligned.m16n8k16.row.col.f32.f16.f16.f32 "
        "{%0,%1,%2,%3}, {%4,%5,%6,%7}, {%8,%9}, {%0,%1,%2,%3};"
        : "+f"(c[0]), "+f"(c[1]), "+f"(c[2]), "+f"(c[3])
        : "r"(a0), "r"(a1), "r"(a2), "r"(a3), "r"(b0), "r"(b1));
}

// W [K,N] fp32 -> Wt [N,K] fp16 (transposed convert)
__global__ void convT_k(const float* __restrict__ W, __half* __restrict__ hi,
                        int K, int N) {
    int idx = blockIdx.x * 256 + threadIdx.x;
    if (idx >= N * K) return;
    int n = idx / K, k = idx - n * K;
    hi[idx] = __float2half_rn(W[(size_t)k * N + n]);
}

// ---------------- HMMA fp16 GEMM: C[M,N] = A[M,K] * B[N,K]^T ---------------------
#define STAGES 3
#define PITCH 80
#define MAT_BYTES (128*PITCH)
#define STAGE_BYTES (2*MAT_BYTES)        // A | B
#define GEMM_SMEM (STAGES*STAGE_BYTES)   // 61440

__global__ void __launch_bounds__(256) gemm_mma(
    const __half* __restrict__ A, const __half* __restrict__ B,
    float* __restrict__ C, int M, int N, int K) {
    extern __shared__ char sm8[];
    const uint32_t sb = smem_u32(sm8);
    const int tid = threadIdx.x;
    const int lane = tid & 31, wid = tid >> 5;
    const int wm = wid & 3, wn = wid >> 2;
    const int bm = blockIdx.y * 128, bn = blockIdx.x * 128;
    const int g = lane >> 2, tig = lane & 3;
    const int NCH = K >> 5;

    const char* pA = (const char*)A;
    const char* pB = (const char*)B;
    const size_t rowb = (size_t)K * 2;

    auto load_stage = [&](int kc, int s) {
        uint32_t sbase = sb + s * STAGE_BYTES;
        size_t kb = (size_t)kc * 64;
#pragma unroll
        for (int i = tid; i < 512; i += 256) {
            int r = i >> 2, gg = i & 3;
            uint32_t so = sbase + r * PITCH + gg * 16;
            size_t ga = (size_t)(bm + r) * rowb + kb + gg * 16;
            size_t gb = (size_t)(bn + r) * rowb + kb + gg * 16;
            cp16(so,             pA + ga);
            cp16(so + MAT_BYTES, pB + gb);
        }
        asm volatile("cp.async.commit_group;" ::: "memory");
    };

    float acc[2][8][4];
#pragma unroll
    for (int f = 0; f < 2; f++)
#pragma unroll
        for (int nf = 0; nf < 8; nf++)
#pragma unroll
            for (int c = 0; c < 4; c++) acc[f][nf][c] = 0.f;

    load_stage(0, 0);
    load_stage(1, 1);

    for (int kc = 0; kc < NCH; kc++) {
        int s = kc % STAGES;
        asm volatile("cp.async.wait_group 1;" ::: "memory");
        __syncthreads();
        if (kc + 2 < NCH) load_stage(kc + 2, (kc + 2) % STAGES);
        else asm volatile("cp.async.commit_group;" ::: "memory");

        uint32_t aA = sb + s * STAGE_BYTES;
        uint32_t aB = aA + MAT_BYTES;
#pragma unroll
        for (int kk = 0; kk < 2; kk++) {
            const uint32_t kof = kk * 32 + tig * 4;
            uint32_t ah[2][4];
#pragma unroll
            for (int f = 0; f < 2; f++) {
                uint32_t r0 = (uint32_t)(wm * 32 + f * 16 + g) * PITCH + kof;
                ah[f][0] = lds32(aA + r0);
                ah[f][1] = lds32(aA + r0 + 8*PITCH);
                ah[f][2] = lds32(aA + r0 + 16);
                ah[f][3] = lds32(aA + r0 + 8*PITCH + 16);
            }
#pragma unroll
            for (int nf = 0; nf < 8; nf++) {
                uint32_t n0 = (uint32_t)(wn * 64 + nf * 8 + g) * PITCH + kof;
                uint32_t bh0 = lds32(aB + n0);
                uint32_t bh1 = lds32(aB + n0 + 16);
#pragma unroll
                for (int f = 0; f < 2; f++)
                    mma16816h(acc[f][nf], ah[f][0], ah[f][1], ah[f][2], ah[f][3], bh0, bh1);
            }
        }
        __syncthreads();
    }

#pragma unroll
    for (int f = 0; f < 2; f++) {
        int r0 = bm + wm * 32 + f * 16 + g;
#pragma unroll
        for (int nf = 0; nf < 8; nf++) {
            int c0 = bn + wn * 64 + nf * 8 + 2 * tig;
            *(float2*)&C[(size_t)r0 * N + c0]       = make_float2(acc[f][nf][0], acc[f][nf][1]);
            *(float2*)&C[(size_t)(r0 + 8) * N + c0] = make_float2(acc[f][nf][2], acc[f][nf][3]);
        }
    }
}

// ---------------- x @ W1  (K=4) ----------------
__global__ void lin1_k(const float* __restrict__ x, const float* __restrict__ W,
                       float* __restrict__ out) {
    int idx = blockIdx.x * 256 + threadIdx.x;
    int n = idx >> 9, f = idx & 511;
    const float* xr = x + n * 4;
    out[idx] = xr[0]*W[f] + xr[1]*W[512+f] + xr[2]*W[1024+f] + xr[3]*W[1536+f];
}

// ---------------- GAT kernel A: attention (atomic-free softmax) ------------------
template <bool LOOPS>
__global__ void __launch_bounds__(256) gat_attn(
    const float* __restrict__ hpre,
    const int* __restrict__ esrc, const int* __restrict__ edst,
    const float* __restrict__ ea,
    const float* __restrict__ a_src, const float* __restrict__ a_dst,
    const float* __restrict__ We, const float* __restrict__ ae,
    float* __restrict__ galpha, int* __restrict__ gsrcb, int* __restrict__ goffb) {
    __shared__ float sh_ssrc[400];
    __shared__ float sh_sdst[400];
    __shared__ float sh_alS[EMAX*8];
    __shared__ float sh_den[400];
    __shared__ float sh_av[1024];
    __shared__ float sh_weae[8];
    __shared__ float sh_easum[52];
    __shared__ int   sh_srcS[EMAX];
    __shared__ int   sh_dstS[EMAX];
    __shared__ int   sh_cnt[52];
    __shared__ int   sh_off[52];
    __shared__ int   sh_cur[52];

    const int g = blockIdx.x;
    const int nb = g * NODES;
    const int eb = g * EPG;
    const int tid = threadIdx.x;
    const int lane = tid & 31, wid = tid >> 5;
    const int ECNT = LOOPS ? (EPG + NODES) : EPG;

    if (tid < NODES) { sh_cnt[tid] = 0; sh_easum[tid] = 0.f; sh_cur[tid] = 0; }
    for (int i = tid; i < 512; i += 256) {
        sh_av[i] = a_src[i];
        sh_av[512 + i] = a_dst[i];
    }
    if (tid < 8) {
        float s = 0.f;
#pragma unroll
        for (int c = 0; c < 64; c++) s += We[tid * 64 + c] * ae[tid * 64 + c];
        sh_weae[tid] = s;
    }
    __syncthreads();

    for (int e = tid; e < EPG; e += 256) {
        int d = edst[eb + e] - nb;
        atomicAdd(&sh_cnt[d], 1);
        atomicAdd(&sh_easum[d], ea[eb + e]);
    }
    __syncthreads();

    // per-(node,head) scores: warp per node, h read from global once
    for (int n = wid; n < NODES; n += 8) {
        const float4* hr = (const float4*)(hpre + (size_t)(nb + n) * FDIM);
#pragma unroll
        for (int k = 0; k < 4; k++) {
            float4 v = hr[lane + 32 * k];
            int f = 4 * lane + 128 * k;
            float4 as = *(const float4*)(sh_av + f);
            float4 ad = *(const float4*)(sh_av + 512 + f);
            float s1 = v.x*as.x + v.y*as.y + v.z*as.z + v.w*as.w;
            float s2 = v.x*ad.x + v.y*ad.y + v.z*ad.z + v.w*ad.w;
#pragma unroll
            for (int o = 8; o > 0; o >>= 1) {
                s1 += __shfl_xor_sync(0xffffffffu, s1, o);
                s2 += __shfl_xor_sync(0xffffffffu, s2, o);
            }
            if ((lane & 15) == 0) {
                int head = 2 * k + (lane >> 4);
                sh_ssrc[n * 8 + head] = s1;
                sh_sdst[n * 8 + head] = s2;
            }
        }
    }
    __syncthreads();

    if (tid == 0) {
        int o = 0;
        for (int n = 0; n < NODES; n++) { sh_off[n] = o; o += sh_cnt[n] + (LOOPS ? 1 : 0); }
    }
    __syncthreads();

    // phase 3: logits (leaky-relu) placed in dst-sorted order (no max atomics)
    for (int e = tid; e < ECNT; e += 256) {
        int sl, dl; float eav;
        if (e < EPG) { sl = esrc[eb + e] - nb; dl = edst[eb + e] - nb; eav = ea[eb + e]; }
        else { sl = dl = e - EPG; eav = sh_easum[dl] / fmaxf((float)sh_cnt[dl], 1.f); }
        int pos = sh_off[dl] + atomicAdd(&sh_cur[dl], 1);
        sh_srcS[pos] = sl; sh_dstS[pos] = dl;
#pragma unroll
        for (int h = 0; h < 8; h++) {
            float al = sh_ssrc[sl * 8 + h] + sh_sdst[dl * 8 + h] + eav * sh_weae[h];
            al = al > 0.f ? al : 0.2f * al;
            sh_alS[pos * 8 + h] = al;
        }
    }
    __syncthreads();

    // phase 4: per-(node,head) scan — max(0,·), exp in place, inverse denom.
    // max(0, max al) is softmax-shift-equivalent to the reference's finite-max.
    for (int p = tid; p < NODES * HEADS; p += 256) {
        int n = p >> 3, h = p & 7;
        const int beg = sh_off[n], end = beg + (LOOPS ? (sh_cnt[n] + 1) : sh_cnt[n]);
        float m = 0.f;
        for (int j = beg; j < end; j++) m = fmaxf(m, sh_alS[j * 8 + h]);
        float d = 0.f;
        for (int j = beg; j < end; j++) {
            float pv = __expf(sh_alS[j * 8 + h] - m);
            sh_alS[j * 8 + h] = pv;
            d += pv;
        }
        sh_den[p] = 1.f / (d + 1e-16f);
    }
    __syncthreads();

    // write normalized alpha + sorted src + offsets to global scratch
    float* ga = galpha + (size_t)g * EMAX * 8;
    int* gs = gsrcb + (size_t)g * EMAX;
    for (int i = tid; i < ECNT; i += 256) {
        int dl = sh_dstS[i];
        float4 o0, o1;
        o0.x = sh_alS[i*8+0] * sh_den[dl*8+0];
        o0.y = sh_alS[i*8+1] * sh_den[dl*8+1];
        o0.z = sh_alS[i*8+2] * sh_den[dl*8+2];
        o0.w = sh_alS[i*8+3] * sh_den[dl*8+3];
        o1.x = sh_alS[i*8+4] * sh_den[dl*8+4];
        o1.y = sh_alS[i*8+5] * sh_den[dl*8+5];
        o1.z = sh_alS[i*8+6] * sh_den[dl*8+6];
        o1.w = sh_alS[i*8+7] * sh_den[dl*8+7];
        ((float4*)(ga + i * 8))[0] = o0;
        ((float4*)(ga + i * 8))[1] = o1;
        gs[i] = sh_srcS[i];
    }
    if (tid < NODES) goffb[g * 51 + tid] = sh_off[tid];
    if (tid == NODES) goffb[g * 51 + NODES] = ECNT;
}

// ---------------- GAT kernel B: aggregation (graph x 128-feature slice) ----------
// Vectorized x4: lane covers 4 consecutive features, warp covers all 128 of slice.
template <bool OUTFP16>
__global__ void __launch_bounds__(256) gat_aggr(
    const float* __restrict__ hpre,
    const float* __restrict__ galpha, const int* __restrict__ gsrcb,
    const int* __restrict__ goffb,
    const float* __restrict__ bias, float* __restrict__ xout,
    __half* __restrict__ outh) {
    __shared__ float sh_hs[NODES * 128];   // 25.6 KB
    __shared__ float sh_al[EMAX * 2];
    __shared__ int   sh_src[EMAX];
    __shared__ int   sh_off[51];

    const int sl = blockIdx.x;     // 0..3
    const int g = blockIdx.y;
    const int nb = g * NODES;
    const int tid = threadIdx.x;
    const int lane = tid & 31, wg = tid >> 5;
    const int ECNT = goffb[g * 51 + NODES];

    for (int i = tid; i < NODES * 128; i += 256) {
        int n = i >> 7, ff = i & 127;
        sh_hs[i] = hpre[(size_t)(nb + n) * FDIM + sl * 128 + ff];
    }
    const float* ga = galpha + (size_t)g * EMAX * 8 + sl * 2;
    const int* gs = gsrcb + (size_t)g * EMAX;
    for (int i = tid; i < ECNT; i += 256) {
        sh_al[i * 2]     = ga[i * 8];
        sh_al[i * 2 + 1] = ga[i * 8 + 1];
        sh_src[i] = gs[i];
    }
    if (tid <= NODES) sh_off[tid] = goffb[g * 51 + tid];
    __syncthreads();

    const int hsel = lane >> 4;
    const int f0 = lane * 4;
    const float4 bv = *(const float4*)(bias + sl * 128 + f0);
    for (int n = wg; n < NODES; n += 8) {
        float4 acc = {0.f, 0.f, 0.f, 0.f};
        const int beg = sh_off[n], end = sh_off[n + 1];
        for (int j = beg; j < end; j++) {
            const int s = sh_src[j];
            const float a = sh_al[j * 2 + hsel];
            const float4 h = *(const float4*)(sh_hs + s * 128 + f0);
            acc.x += a * h.x; acc.y += a * h.y;
            acc.z += a * h.z; acc.w += a * h.w;
        }
        float4 v;
        v.x = fmaxf(acc.x + bv.x, 0.f);
        v.y = fmaxf(acc.y + bv.y, 0.f);
        v.z = fmaxf(acc.z + bv.z, 0.f);
        v.w = fmaxf(acc.w + bv.w, 0.f);
        size_t idx = (size_t)(nb + n) * FDIM + sl * 128 + f0;
        if (OUTFP16) {
            __half2* op = (__half2*)(outh + idx);
            op[0] = __floats2half2_rn(v.x, v.y);
            op[1] = __floats2half2_rn(v.z, v.w);
        } else {
            *(float4*)(xout + idx) = v;
        }
    }
}

// ---------------- mean pool -> fp16 graph-emb half of GRU operand ----------------
__global__ void pool_k(const float* __restrict__ x3, __half* __restrict__ Ah) {
    int b = blockIdx.x;
    int f = blockIdx.y * 128 + threadIdx.x;
    float s = 0.f;
#pragma unroll 10
    for (int n = 0; n < NODES; n++) s += x3[(size_t)(b * NODES + n) * FDIM + f];
    s *= (1.f / 50.f);
    __half h = __float2half_rn(s);
#pragma unroll
    for (int t = 0; t < NA; t++)
        Ah[(size_t)(b * NA + t) * GRUI + 512 + f] = h;
}

// ---------------- agent rows -> fp16 agent half of GRU operand -------------------
__global__ void agent_k(const float* __restrict__ x3, __half* __restrict__ Ah) {
    int r = blockIdx.x;           // b*5 + t
    int b = r / 5, t = r - b * 5;
    for (int f = threadIdx.x; f < 512; f += 128)
        Ah[(size_t)r * GRUI + f] =
            __float2half_rn(x3[(size_t)(b * NODES + t) * FDIM + f]);
}

// ---------------- GRU: GH = h @ Whh ----------------
__global__ void gru_gh_k(const float* __restrict__ h, const float* __restrict__ Whh,
                         float* __restrict__ GH) {
    __shared__ float hs[8 * GRUH];
    int b0 = blockIdx.x * 8;
    int tid = threadIdx.x;
    for (int i = tid; i < 8 * GRUH; i += 384) hs[i] = h[b0 * GRUH + i];
    __syncthreads();
    float acc[8];
#pragma unroll
    for (int r = 0; r < 8; r++) acc[r] = 0.f;
    for (int k = 0; k < GRUH; k++) {
        float w = Whh[k * G3 + tid];
#pragma unroll
        for (int r = 0; r < 8; r++) acc[r] += hs[r * GRUH + k] * w;
    }
#pragma unroll
    for (int r = 0; r < 8; r++) GH[(b0 + r) * G3 + tid] = acc[r];
}

// ---------------- GRU gate math ----------------
__global__ void gru_gate_k(const float* __restrict__ GI, int t,
                           const float* __restrict__ GHb, const float* __restrict__ hprev,
                           const float* __restrict__ bih, const float* __restrict__ bhh,
                           float* __restrict__ hnew, float* __restrict__ gout,
                           float* __restrict__ hlast) {
    int b = blockIdx.x, j = threadIdx.x;
    const float* gi = GI + (size_t)(b * NA + t) * G3;
    const float* gh = GHb + (size_t)b * G3;
    float ir = gi[j] + bih[j];
    float iz = gi[j + 128] + bih[j + 128];
    float in_ = gi[j + 256] + bih[j + 256];
    float hr = gh[j] + bhh[j];
    float hz = gh[j + 128] + bhh[j + 128];
    float hn = gh[j + 256] + bhh[j + 256];
    float r = 1.f / (1.f + expf(-(ir + hr)));
    float z = 1.f / (1.f + expf(-(iz + hz)));
    float nn = tanhf(in_ + r * hn);
    float hp = hprev[b * GRUH + j];
    float h = (1.f - z) * nn + z * hp;
    hnew[b * GRUH + j] = h;
    gout[(size_t)(b * NA + t) * GRUH + j] = h;
    if (hlast) hlast[b * GRUH + j] = h;
}

// ---------------- FC head ----------------
__global__ void fc_k(const float* __restrict__ gout, const float* __restrict__ W1,
                     const float* __restrict__ b1, const float* __restrict__ W2,
                     const float* __restrict__ b2, const float* __restrict__ ls,
                     float* __restrict__ out) {
    __shared__ float g[128];
    __shared__ float f1[64];
    int r = blockIdx.x, tid = threadIdx.x;
    g[tid] = gout[(size_t)r * GRUH + tid];
    g[tid + 64] = gout[(size_t)r * GRUH + tid + 64];
    __syncthreads();
    float acc = b1[tid];
#pragma unroll 8
    for (int k = 0; k < 128; k++) acc += g[k] * W1[k * 64 + tid];
    f1[tid] = acc > 0.f ? acc : 0.f;
    __syncthreads();
    if (tid < 3) {
        float a2 = b2[tid];
#pragma unroll
        for (int k = 0; k < 64; k++) a2 += f1[k] * W2[k * 3 + tid];
        out[r * 3 + tid] = a2;
        float l = ls[tid];
        l = fminf(fmaxf(l, -20.f), 2.f);
        out[NGRAPH * NA * 3 + r * 3 + tid] = expf(l);
    }
}

// ---------------- launch ----------------
extern "C" void kernel_launch(void* const* d_in, const int* in_sizes, int n_in,
                              void* d_out, int out_size) {
    const float* x      = (const float*)d_in[0];
    const int*   ei     = (const int*)d_in[1];
    const float* ea     = (const float*)d_in[2];
    const float* hid0   = (const float*)d_in[3];
    const float* W1     = (const float*)d_in[4];
    const float* a_s1   = (const float*)d_in[5];
    const float* a_d1   = (const float*)d_in[6];
    const float* We1    = (const float*)d_in[7];
    const float* ae1    = (const float*)d_in[8];
    const float* b1     = (const float*)d_in[9];
    const float* W2     = (const float*)d_in[10];
    const float* a_s2   = (const float*)d_in[11];
    const float* a_d2   = (const float*)d_in[12];
    const float* We2    = (const float*)d_in[13];
    const float* ae2    = (const float*)d_in[14];
    const float* b2     = (const float*)d_in[15];
    const float* W3     = (const float*)d_in[16];
    const float* a_s3   = (const float*)d_in[17];
    const float* a_d3   = (const float*)d_in[18];
    const float* We3    = (const float*)d_in[19];
    const float* ae3    = (const float*)d_in[20];
    const float* b3     = (const float*)d_in[21];
    const float* Wih    = (const float*)d_in[22];
    const float* Whh    = (const float*)d_in[23];
    const float* bih    = (const float*)d_in[24];
    const float* bhh    = (const float*)d_in[25];
    const float* fc1W   = (const float*)d_in[26];
    const float* fc1b   = (const float*)d_in[27];
    const float* fc2W   = (const float*)d_in[28];
    const float* fc2b   = (const float*)d_in[29];
    const float* logstd = (const float*)d_in[30];
    float* out = (float*)d_out;

    float *bufA, *bufB, *GI, *GHb, *h0b, *h1b, *gout, *alphab;
    int *srcb, *offb;
    __half *Ah, *Bh;
    cudaGetSymbolAddress((void**)&bufA, g_bufA);
    cudaGetSymbolAddress((void**)&bufB, g_bufB);
    cudaGetSymbolAddress((void**)&GI,   g_GI);
    cudaGetSymbolAddress((void**)&GHb,  g_GHbuf);
    cudaGetSymbolAddress((void**)&h0b,  g_h0);
    cudaGetSymbolAddress((void**)&h1b,  g_h1);
    cudaGetSymbolAddress((void**)&gout, g_gruout);
    cudaGetSymbolAddress((void**)&alphab, g_alpha);
    cudaGetSymbolAddress((void**)&srcb, g_srcb);
    cudaGetSymbolAddress((void**)&offb, g_offb);
    cudaGetSymbolAddress((void**)&Ah, g_Ah);
    cudaGetSymbolAddress((void**)&Bh, g_Bh);

    cudaFuncSetAttribute((const void*)gemm_mma,
                         cudaFuncAttributeMaxDynamicSharedMemorySize, GEMM_SMEM);

    const int* esrc = ei;
    const int* edst = ei + NE;

    // layer 1 -> fp16 A operand directly
    lin1_k<<<(NN * FDIM) / 256, 256>>>(x, W1, bufA);
    gat_attn<false><<<NGRAPH, 256>>>(bufA, esrc, edst, ea, a_s1, a_d1, We1, ae1,
                                     alphab, srcb, offb);
    gat_aggr<true><<<dim3(4, NGRAPH), 256>>>(bufA, alphab, srcb, offb, b1,
                                             nullptr, Ah);
    // layer 2
    convT_k<<<(FDIM * FDIM + 255) / 256, 256>>>(W2, Bh, FDIM, FDIM);
    gemm_mma<<<dim3(FDIM / 128, NN / 128), 256, GEMM_SMEM>>>(Ah, Bh, bufA,
                                                             NN, FDIM, FDIM);
    gat_attn<true><<<NGRAPH, 256>>>(bufA, esrc, edst, ea, a_s2, a_d2, We2, ae2,
                                    alphab, srcb, offb);
    gat_aggr<true><<<dim3(4, NGRAPH), 256>>>(bufA, alphab, srcb, offb, b2,
                                             nullptr, Ah);
    // layer 3 -> fp32 (feeds pool/agent)
    convT_k<<<(FDIM * FDIM + 255) / 256, 256>>>(W3, Bh, FDIM, FDIM);
    gemm_mma<<<dim3(FDIM / 128, NN / 128), 256, GEMM_SMEM>>>(Ah, Bh, bufA,
                                                             NN, FDIM, FDIM);
    gat_attn<true><<<NGRAPH, 256>>>(bufA, esrc, edst, ea, a_s3, a_d3, We3, ae3,
                                    alphab, srcb, offb);
    gat_aggr<false><<<dim3(4, NGRAPH), 256>>>(bufA, alphab, srcb, offb, b3,
                                              bufB, nullptr);
    // pooling + agent rows -> GRU GEMM A operand (fp16), then GI GEMM
    pool_k<<<dim3(NGRAPH, FDIM / 128), 128>>>(bufB, Ah);
    agent_k<<<NGRAPH * NA, 128>>>(bufB, Ah);
    convT_k<<<(GRUI * G3 + 255) / 256, 256>>>(Wih, Bh, GRUI, G3);
    gemm_mma<<<dim3(G3 / 128, (NGRAPH * NA) / 128), 256, GEMM_SMEM>>>(
        Ah, Bh, GI, NGRAPH * NA, G3, GRUI);
    // GRU recurrence (10-launch — frozen)
    cudaMemcpyAsync(h0b, hid0, (size_t)NGRAPH * GRUH * sizeof(float),
                    cudaMemcpyDeviceToDevice);
    for (int t = 0; t < NA; t++) {
        float* hc = (t & 1) ? h1b : h0b;
        float* hn = (t & 1) ? h0b : h1b;
        gru_gh_k<<<NGRAPH / 8, G3>>>(hc, Whh, GHb);
        gru_gate_k<<<NGRAPH, GRUH>>>(GI, t, GHb, hc, bih, bhh, hn, gout,
                                     (t == NA - 1) ? (out + NGRAPH * NA * 3 * 2) : nullptr);
    }
    fc_k<<<NGRAPH * NA, 64>>>(gout, fc1W, fc1b, fc2W, fc2b, logstd, out);
}

// round 15
// speedup vs baseline: 1.9693x; 1.0473x over previous
#include <cuda_runtime.h>
#include <cuda_fp16.h>
#include <cstdint>

#define NODES 50
#define EPG   400
#define NGRAPH 512
#define NN    (NGRAPH*NODES)   // 25600
#define NE    (NGRAPH*EPG)     // 204800
#define FDIM  512
#define HEADS 8
#define CH    64
#define NA    5
#define GRUH  128
#define GRUI  1024
#define G3    384
#define EMAX  456              // padded per-graph edge capacity (450 used)

// ---------------- scratch (static device globals; no allocation) ----------------
__device__ __half g_Hh[NN*FDIM];        // node features (GAT layer input), fp16
__device__ float g_bufB[NN*FDIM];       // layer-3 output fp32 (pool/agent input)
__device__ __half g_Ah[NN*FDIM];        // GEMM A operand
__device__ __half g_Bh[GRUI*G3 > FDIM*FDIM ? GRUI*G3 : FDIM*FDIM];
__device__ float g_alpha[NGRAPH*EMAX*HEADS];
__device__ int   g_srcb[NGRAPH*EMAX];
__device__ int   g_offb[NGRAPH*51];
__device__ float g_GI[NGRAPH*NA*G3];
__device__ float g_GHbuf[NGRAPH*G3];
__device__ float g_h0[NGRAPH*GRUH];
__device__ float g_h1[NGRAPH*GRUH];
__device__ float g_gruout[NGRAPH*NA*GRUH];

// ---------------- helpers ----------------
__device__ __forceinline__ uint32_t smem_u32(const void* p) {
    uint32_t a;
    asm("{ .reg .u64 t; cvta.to.shared.u64 t, %1; cvt.u32.u64 %0, t; }" : "=r"(a) : "l"(p));
    return a;
}
__device__ __forceinline__ void cp16(uint32_t sdst, const void* gsrc) {
    asm volatile("cp.async.cg.shared.global [%0], [%1], 16;" :: "r"(sdst), "l"(gsrc) : "memory");
}
__device__ __forceinline__ uint32_t lds32(uint32_t a) {
    uint32_t v;
    asm volatile("ld.shared.b32 %0, [%1];" : "=r"(v) : "r"(a));
    return v;
}
__device__ __forceinline__ void mma16816h(float* c, uint32_t a0, uint32_t a1,
                                          uint32_t a2, uint32_t a3,
                                          uint32_t b0, uint32_t b1) {
    asm volatile(
        "mma.sync.aligned.m16n8k16.row.col.f32.f16.f16.f32 "
        "{%0,%1,%2,%3}, {%4,%5,%6,%7}, {%8,%9}, {%0,%1,%2,%3};"
        : "+f"(c[0]), "+f"(c[1]), "+f"(c[2]), "+f"(c[3])
        : "r"(a0), "r"(a1), "r"(a2), "r"(a3), "r"(b0), "r"(b1));
}

// W [K,N] fp32 -> Wt [N,K] fp16 (transposed convert)
__global__ void convT_k(const float* __restrict__ W, __half* __restrict__ hi,
                        int K, int N) {
    int idx = blockIdx.x * 256 + threadIdx.x;
    if (idx >= N * K) return;
    int n = idx / K, k = idx - n * K;
    hi[idx] = __float2half_rn(W[(size_t)k * N + n]);
}

// ---------------- HMMA fp16 GEMM: C = A[M,K] * B[N,K]^T; fp32 or fp16 out --------
#define STAGES 3
#define PITCH 80
#define MAT_BYTES (128*PITCH)
#define STAGE_BYTES (2*MAT_BYTES)        // A | B
#define GEMM_SMEM (STAGES*STAGE_BYTES)   // 61440

template <bool OUTHALF>
__global__ void __launch_bounds__(256) gemm_mma(
    const __half* __restrict__ A, const __half* __restrict__ B,
    float* __restrict__ C, __half* __restrict__ Ch, int M, int N, int K) {
    extern __shared__ char sm8[];
    const uint32_t sb = smem_u32(sm8);
    const int tid = threadIdx.x;
    const int lane = tid & 31, wid = tid >> 5;
    const int wm = wid & 3, wn = wid >> 2;
    const int bm = blockIdx.y * 128, bn = blockIdx.x * 128;
    const int g = lane >> 2, tig = lane & 3;
    const int NCH = K >> 5;

    const char* pA = (const char*)A;
    const char* pB = (const char*)B;
    const size_t rowb = (size_t)K * 2;

    auto load_stage = [&](int kc, int s) {
        uint32_t sbase = sb + s * STAGE_BYTES;
        size_t kb = (size_t)kc * 64;
#pragma unroll
        for (int i = tid; i < 512; i += 256) {
            int r = i >> 2, gg = i & 3;
            uint32_t so = sbase + r * PITCH + gg * 16;
            size_t ga = (size_t)(bm + r) * rowb + kb + gg * 16;
            size_t gb = (size_t)(bn + r) * rowb + kb + gg * 16;
            cp16(so,             pA + ga);
            cp16(so + MAT_BYTES, pB + gb);
        }
        asm volatile("cp.async.commit_group;" ::: "memory");
    };

    float acc[2][8][4];
#pragma unroll
    for (int f = 0; f < 2; f++)
#pragma unroll
        for (int nf = 0; nf < 8; nf++)
#pragma unroll
            for (int c = 0; c < 4; c++) acc[f][nf][c] = 0.f;

    load_stage(0, 0);
    load_stage(1, 1);

    for (int kc = 0; kc < NCH; kc++) {
        int s = kc % STAGES;
        asm volatile("cp.async.wait_group 1;" ::: "memory");
        __syncthreads();
        if (kc + 2 < NCH) load_stage(kc + 2, (kc + 2) % STAGES);
        else asm volatile("cp.async.commit_group;" ::: "memory");

        uint32_t aA = sb + s * STAGE_BYTES;
        uint32_t aB = aA + MAT_BYTES;
#pragma unroll
        for (int kk = 0; kk < 2; kk++) {
            const uint32_t kof = kk * 32 + tig * 4;
            uint32_t ah[2][4];
#pragma unroll
            for (int f = 0; f < 2; f++) {
                uint32_t r0 = (uint32_t)(wm * 32 + f * 16 + g) * PITCH + kof;
                ah[f][0] = lds32(aA + r0);
                ah[f][1] = lds32(aA + r0 + 8*PITCH);
                ah[f][2] = lds32(aA + r0 + 16);
                ah[f][3] = lds32(aA + r0 + 8*PITCH + 16);
            }
#pragma unroll
            for (int nf = 0; nf < 8; nf++) {
                uint32_t n0 = (uint32_t)(wn * 64 + nf * 8 + g) * PITCH + kof;
                uint32_t bh0 = lds32(aB + n0);
                uint32_t bh1 = lds32(aB + n0 + 16);
#pragma unroll
                for (int f = 0; f < 2; f++)
                    mma16816h(acc[f][nf], ah[f][0], ah[f][1], ah[f][2], ah[f][3], bh0, bh1);
            }
        }
        __syncthreads();
    }

#pragma unroll
    for (int f = 0; f < 2; f++) {
        int r0 = bm + wm * 32 + f * 16 + g;
#pragma unroll
        for (int nf = 0; nf < 8; nf++) {
            int c0 = bn + wn * 64 + nf * 8 + 2 * tig;
            if (OUTHALF) {
                *(__half2*)&Ch[(size_t)r0 * N + c0] =
                    __floats2half2_rn(acc[f][nf][0], acc[f][nf][1]);
                *(__half2*)&Ch[(size_t)(r0 + 8) * N + c0] =
                    __floats2half2_rn(acc[f][nf][2], acc[f][nf][3]);
            } else {
                *(float2*)&C[(size_t)r0 * N + c0]       = make_float2(acc[f][nf][0], acc[f][nf][1]);
                *(float2*)&C[(size_t)(r0 + 8) * N + c0] = make_float2(acc[f][nf][2], acc[f][nf][3]);
            }
        }
    }
}

// ---------------- x @ W1  (K=4) -> fp16, 2 features per thread ----------------
__global__ void lin1_k(const float* __restrict__ x, const float* __restrict__ W,
                       __half* __restrict__ out) {
    int idx = blockIdx.x * 256 + threadIdx.x;     // NN*256 threads
    int n = idx >> 8, f = (idx & 255) * 2;
    float4 xv = *(const float4*)(x + (size_t)n * 4);
    float v0 = xv.x*W[f]   + xv.y*W[512+f]   + xv.z*W[1024+f]   + xv.w*W[1536+f];
    float v1 = xv.x*W[f+1] + xv.y*W[512+f+1] + xv.z*W[1024+f+1] + xv.w*W[1536+f+1];
    *(__half2*)&out[(size_t)n * FDIM + f] = __floats2half2_rn(v0, v1);
}

// ---------------- GAT kernel A: attention (fp16 hpre; atomic-free softmax) -------
template <bool LOOPS>
__global__ void __launch_bounds__(256) gat_attn(
    const __half* __restrict__ hpre,
    const int* __restrict__ esrc, const int* __restrict__ edst,
    const float* __restrict__ ea,
    const float* __restrict__ a_src, const float* __restrict__ a_dst,
    const float* __restrict__ We, const float* __restrict__ ae,
    float* __restrict__ galpha, int* __restrict__ gsrcb, int* __restrict__ goffb) {
    __shared__ float sh_ssrc[400];
    __shared__ float sh_sdst[400];
    __shared__ float sh_alS[EMAX*8];
    __shared__ float sh_den[400];
    __shared__ float sh_av[1024];
    __shared__ float sh_weae[8];
    __shared__ float sh_easum[52];
    __shared__ int   sh_srcS[EMAX];
    __shared__ int   sh_dstS[EMAX];
    __shared__ int   sh_cnt[52];
    __shared__ int   sh_off[52];
    __shared__ int   sh_cur[52];

    const int g = blockIdx.x;
    const int nb = g * NODES;
    const int eb = g * EPG;
    const int tid = threadIdx.x;
    const int lane = tid & 31, wid = tid >> 5;
    const int ECNT = LOOPS ? (EPG + NODES) : EPG;

    if (tid < NODES) { sh_cnt[tid] = 0; sh_easum[tid] = 0.f; sh_cur[tid] = 0; }
    for (int i = tid; i < 512; i += 256) {
        sh_av[i] = a_src[i];
        sh_av[512 + i] = a_dst[i];
    }
    if (tid < 8) {
        float s = 0.f;
#pragma unroll
        for (int c = 0; c < 64; c++) s += We[tid * 64 + c] * ae[tid * 64 + c];
        sh_weae[tid] = s;
    }
    __syncthreads();

    for (int e = tid; e < EPG; e += 256) {
        int d = edst[eb + e] - nb;
        atomicAdd(&sh_cnt[d], 1);
        atomicAdd(&sh_easum[d], ea[eb + e]);
    }
    __syncthreads();

    // per-(node,head) scores: warp per node, fp16 h read from global once
    for (int n = wid; n < NODES; n += 8) {
        const uint2* hr = (const uint2*)(hpre + (size_t)(nb + n) * FDIM);
#pragma unroll
        for (int k = 0; k < 4; k++) {
            uint2 u = hr[lane + 32 * k];
            float2 f01 = __half22float2(*(__half2*)&u.x);
            float2 f23 = __half22float2(*(__half2*)&u.y);
            int f = 4 * lane + 128 * k;
            float4 as = *(const float4*)(sh_av + f);
            float4 ad = *(const float4*)(sh_av + 512 + f);
            float s1 = f01.x*as.x + f01.y*as.y + f23.x*as.z + f23.y*as.w;
            float s2 = f01.x*ad.x + f01.y*ad.y + f23.x*ad.z + f23.y*ad.w;
#pragma unroll
            for (int o = 8; o > 0; o >>= 1) {
                s1 += __shfl_xor_sync(0xffffffffu, s1, o);
                s2 += __shfl_xor_sync(0xffffffffu, s2, o);
            }
            if ((lane & 15) == 0) {
                int head = 2 * k + (lane >> 4);
                sh_ssrc[n * 8 + head] = s1;
                sh_sdst[n * 8 + head] = s2;
            }
        }
    }
    __syncthreads();

    if (tid == 0) {
        int o = 0;
        for (int n = 0; n < NODES; n++) { sh_off[n] = o; o += sh_cnt[n] + (LOOPS ? 1 : 0); }
    }
    __syncthreads();

    // logits (leaky-relu) placed in dst-sorted order
    for (int e = tid; e < ECNT; e += 256) {
        int sl, dl; float eav;
        if (e < EPG) { sl = esrc[eb + e] - nb; dl = edst[eb + e] - nb; eav = ea[eb + e]; }
        else { sl = dl = e - EPG; eav = sh_easum[dl] / fmaxf((float)sh_cnt[dl], 1.f); }
        int pos = sh_off[dl] + atomicAdd(&sh_cur[dl], 1);
        sh_srcS[pos] = sl; sh_dstS[pos] = dl;
#pragma unroll
        for (int h = 0; h < 8; h++) {
            float al = sh_ssrc[sl * 8 + h] + sh_sdst[dl * 8 + h] + eav * sh_weae[h];
            al = al > 0.f ? al : 0.2f * al;
            sh_alS[pos * 8 + h] = al;
        }
    }
    __syncthreads();

    // per-(node,head) scan softmax: max(0,.) is shift-equivalent to reference
    for (int p = tid; p < NODES * HEADS; p += 256) {
        int n = p >> 3, h = p & 7;
        const int beg = sh_off[n], end = beg + (LOOPS ? (sh_cnt[n] + 1) : sh_cnt[n]);
        float m = 0.f;
        for (int j = beg; j < end; j++) m = fmaxf(m, sh_alS[j * 8 + h]);
        float d = 0.f;
        for (int j = beg; j < end; j++) {
            float pv = __expf(sh_alS[j * 8 + h] - m);
            sh_alS[j * 8 + h] = pv;
            d += pv;
        }
        sh_den[p] = 1.f / (d + 1e-16f);
    }
    __syncthreads();

    float* ga = galpha + (size_t)g * EMAX * 8;
    int* gs = gsrcb + (size_t)g * EMAX;
    for (int i = tid; i < ECNT; i += 256) {
        int dl = sh_dstS[i];
        float4 o0, o1;
        o0.x = sh_alS[i*8+0] * sh_den[dl*8+0];
        o0.y = sh_alS[i*8+1] * sh_den[dl*8+1];
        o0.z = sh_alS[i*8+2] * sh_den[dl*8+2];
        o0.w = sh_alS[i*8+3] * sh_den[dl*8+3];
        o1.x = sh_alS[i*8+4] * sh_den[dl*8+4];
        o1.y = sh_alS[i*8+5] * sh_den[dl*8+5];
        o1.z = sh_alS[i*8+6] * sh_den[dl*8+6];
        o1.w = sh_alS[i*8+7] * sh_den[dl*8+7];
        ((float4*)(ga + i * 8))[0] = o0;
        ((float4*)(ga + i * 8))[1] = o1;
        gs[i] = sh_srcS[i];
    }
    if (tid < NODES) goffb[g * 51 + tid] = sh_off[tid];
    if (tid == NODES) goffb[g * 51 + NODES] = ECNT;
}

// ---------------- GAT kernel B: aggregation (fp16 hpre; x4-vectorized) -----------
template <bool OUTFP16>
__global__ void __launch_bounds__(256) gat_aggr(
    const __half* __restrict__ hpre,
    const float* __restrict__ galpha, const int* __restrict__ gsrcb,
    const int* __restrict__ goffb,
    const float* __restrict__ bias, float* __restrict__ xout,
    __half* __restrict__ outh) {
    __shared__ float sh_hs[NODES * 128];   // 25.6 KB (fp32 for fast inner loop)
    __shared__ float sh_al[EMAX * 2];
    __shared__ int   sh_src[EMAX];
    __shared__ int   sh_off[51];

    const int sl = blockIdx.x;     // 0..3
    const int g = blockIdx.y;
    const int nb = g * NODES;
    const int tid = threadIdx.x;
    const int lane = tid & 31, wg = tid >> 5;
    const int ECNT = goffb[g * 51 + NODES];

    // fill smem: 3200 half2 loads across CTA
    for (int i = tid; i < NODES * 64; i += 256) {
        int n = i >> 6, ff2 = i & 63;
        __half2 v = *(const __half2*)(hpre + (size_t)(nb + n) * FDIM + sl * 128 + ff2 * 2);
        float2 f = __half22float2(v);
        sh_hs[n * 128 + ff2 * 2]     = f.x;
        sh_hs[n * 128 + ff2 * 2 + 1] = f.y;
    }
    const float* ga = galpha + (size_t)g * EMAX * 8 + sl * 2;
    const int* gs = gsrcb + (size_t)g * EMAX;
    for (int i = tid; i < ECNT; i += 256) {
        sh_al[i * 2]     = ga[i * 8];
        sh_al[i * 2 + 1] = ga[i * 8 + 1];
        sh_src[i] = gs[i];
    }
    if (tid <= NODES) sh_off[tid] = goffb[g * 51 + tid];
    __syncthreads();

    const int hsel = lane >> 4;
    const int f0 = lane * 4;
    const float4 bv = *(const float4*)(bias + sl * 128 + f0);
    for (int n = wg; n < NODES; n += 8) {
        float4 acc = {0.f, 0.f, 0.f, 0.f};
        const int beg = sh_off[n], end = sh_off[n + 1];
        for (int j = beg; j < end; j++) {
            const int s = sh_src[j];
            const float a = sh_al[j * 2 + hsel];
            const float4 h = *(const float4*)(sh_hs + s * 128 + f0);
            acc.x += a * h.x; acc.y += a * h.y;
            acc.z += a * h.z; acc.w += a * h.w;
        }
        float4 v;
        v.x = fmaxf(acc.x + bv.x, 0.f);
        v.y = fmaxf(acc.y + bv.y, 0.f);
        v.z = fmaxf(acc.z + bv.z, 0.f);
        v.w = fmaxf(acc.w + bv.w, 0.f);
        size_t idx = (size_t)(nb + n) * FDIM + sl * 128 + f0;
        if (OUTFP16) {
            __half2* op = (__half2*)(outh + idx);
            op[0] = __floats2half2_rn(v.x, v.y);
            op[1] = __floats2half2_rn(v.z, v.w);
        } else {
            *(float4*)(xout + idx) = v;
        }
    }
}

// ---------------- fused pool + agent rows -> fp16 GRU GEMM operand ---------------
__global__ void poolagent_k(const float* __restrict__ x3, __half* __restrict__ Ah) {
    int b = blockIdx.x;
    int f = blockIdx.y * 128 + threadIdx.x;
    float s = 0.f;
#pragma unroll 10
    for (int n = 0; n < NODES; n++) {
        float v = x3[(size_t)(b * NODES + n) * FDIM + f];
        s += v;
        if (n < NA)
            Ah[(size_t)(b * NA + n) * GRUI + f] = __float2half_rn(v);
    }
    __half h = __float2half_rn(s * (1.f / 50.f));
#pragma unroll
    for (int t = 0; t < NA; t++)
        Ah[(size_t)(b * NA + t) * GRUI + 512 + f] = h;
}

// ---------------- GRU: GH = h @ Whh ----------------
__global__ void gru_gh_k(const float* __restrict__ h, const float* __restrict__ Whh,
                         float* __restrict__ GH) {
    __shared__ float hs[8 * GRUH];
    int b0 = blockIdx.x * 8;
    int tid = threadIdx.x;
    for (int i = tid; i < 8 * GRUH; i += 384) hs[i] = h[b0 * GRUH + i];
    __syncthreads();
    float acc[8];
#pragma unroll
    for (int r = 0; r < 8; r++) acc[r] = 0.f;
    for (int k = 0; k < GRUH; k++) {
        float w = Whh[k * G3 + tid];
#pragma unroll
        for (int r = 0; r < 8; r++) acc[r] += hs[r * GRUH + k] * w;
    }
#pragma unroll
    for (int r = 0; r < 8; r++) GH[(b0 + r) * G3 + tid] = acc[r];
}

// ---------------- GRU gate math ----------------
__global__ void gru_gate_k(const float* __restrict__ GI, int t,
                           const float* __restrict__ GHb, const float* __restrict__ hprev,
                           const float* __restrict__ bih, const float* __restrict__ bhh,
                           float* __restrict__ hnew, float* __restrict__ gout,
                           float* __restrict__ hlast) {
    int b = blockIdx.x, j = threadIdx.x;
    const float* gi = GI + (size_t)(b * NA + t) * G3;
    const float* gh = GHb + (size_t)b * G3;
    float ir = gi[j] + bih[j];
    float iz = gi[j + 128] + bih[j + 128];
    float in_ = gi[j + 256] + bih[j + 256];
    float hr = gh[j] + bhh[j];
    float hz = gh[j + 128] + bhh[j + 128];
    float hn = gh[j + 256] + bhh[j + 256];
    float r = 1.f / (1.f + expf(-(ir + hr)));
    float z = 1.f / (1.f + expf(-(iz + hz)));
    float nn = tanhf(in_ + r * hn);
    float hp = hprev[b * GRUH + j];
    float h = (1.f - z) * nn + z * hp;
    hnew[b * GRUH + j] = h;
    gout[(size_t)(b * NA + t) * GRUH + j] = h;
    if (hlast) hlast[b * GRUH + j] = h;
}

// ---------------- FC head ----------------
__global__ void fc_k(const float* __restrict__ gout, const float* __restrict__ W1,
                     const float* __restrict__ b1, const float* __restrict__ W2,
                     const float* __restrict__ b2, const float* __restrict__ ls,
                     float* __restrict__ out) {
    __shared__ float g[128];
    __shared__ float f1[64];
    int r = blockIdx.x, tid = threadIdx.x;
    g[tid] = gout[(size_t)r * GRUH + tid];
    g[tid + 64] = gout[(size_t)r * GRUH + tid + 64];
    __syncthreads();
    float acc = b1[tid];
#pragma unroll 8
    for (int k = 0; k < 128; k++) acc += g[k] * W1[k * 64 + tid];
    f1[tid] = acc > 0.f ? acc : 0.f;
    __syncthreads();
    if (tid < 3) {
        float a2 = b2[tid];
#pragma unroll
        for (int k = 0; k < 64; k++) a2 += f1[k] * W2[k * 3 + tid];
        out[r * 3 + tid] = a2;
        float l = ls[tid];
        l = fminf(fmaxf(l, -20.f), 2.f);
        out[NGRAPH * NA * 3 + r * 3 + tid] = expf(l);
    }
}

// ---------------- launch ----------------
extern "C" void kernel_launch(void* const* d_in, const int* in_sizes, int n_in,
                              void* d_out, int out_size) {
    const float* x      = (const float*)d_in[0];
    const int*   ei     = (const int*)d_in[1];
    const float* ea     = (const float*)d_in[2];
    const float* hid0   = (const float*)d_in[3];
    const float* W1     = (const float*)d_in[4];
    const float* a_s1   = (const float*)d_in[5];
    const float* a_d1   = (const float*)d_in[6];
    const float* We1    = (const float*)d_in[7];
    const float* ae1    = (const float*)d_in[8];
    const float* b1     = (const float*)d_in[9];
    const float* W2     = (const float*)d_in[10];
    const float* a_s2   = (const float*)d_in[11];
    const float* a_d2   = (const float*)d_in[12];
    const float* We2    = (const float*)d_in[13];
    const float* ae2    = (const float*)d_in[14];
    const float* b2     = (const float*)d_in[15];
    const float* W3     = (const float*)d_in[16];
    const float* a_s3   = (const float*)d_in[17];
    const float* a_d3   = (const float*)d_in[18];
    const float* We3    = (const float*)d_in[19];
    const float* ae3    = (const float*)d_in[20];
    const float* b3     = (const float*)d_in[21];
    const float* Wih    = (const float*)d_in[22];
    const float* Whh    = (const float*)d_in[23];
    const float* bih    = (const float*)d_in[24];
    const float* bhh    = (const float*)d_in[25];
    const float* fc1W   = (const float*)d_in[26];
    const float* fc1b   = (const float*)d_in[27];
    const float* fc2W   = (const float*)d_in[28];
    const float* fc2b   = (const float*)d_in[29];
    const float* logstd = (const float*)d_in[30];
    float* out = (float*)d_out;

    float *bufB, *GI, *GHb, *h0b, *h1b, *gout, *alphab;
    int *srcb, *offb;
    __half *Hh, *Ah, *Bh;
    cudaGetSymbolAddress((void**)&Hh,   g_Hh);
    cudaGetSymbolAddress((void**)&bufB, g_bufB);
    cudaGetSymbolAddress((void**)&GI,   g_GI);
    cudaGetSymbolAddress((void**)&GHb,  g_GHbuf);
    cudaGetSymbolAddress((void**)&h0b,  g_h0);
    cudaGetSymbolAddress((void**)&h1b,  g_h1);
    cudaGetSymbolAddress((void**)&gout, g_gruout);
    cudaGetSymbolAddress((void**)&alphab, g_alpha);
    cudaGetSymbolAddress((void**)&srcb, g_srcb);
    cudaGetSymbolAddress((void**)&offb, g_offb);
    cudaGetSymbolAddress((void**)&Ah, g_Ah);
    cudaGetSymbolAddress((void**)&Bh, g_Bh);

    cudaFuncSetAttribute((const void*)gemm_mma<false>,
                         cudaFuncAttributeMaxDynamicSharedMemorySize, GEMM_SMEM);
    cudaFuncSetAttribute((const void*)gemm_mma<true>,
                         cudaFuncAttributeMaxDynamicSharedMemorySize, GEMM_SMEM);

    const int* esrc = ei;
    const int* edst = ei + NE;

    // layer 1: lin1 -> fp16 Hh; attn+aggr -> fp16 Ah
    lin1_k<<<NN, 256>>>(x, W1, Hh);
    gat_attn<false><<<NGRAPH, 256>>>(Hh, esrc, edst, ea, a_s1, a_d1, We1, ae1,
                                     alphab, srcb, offb);
    gat_aggr<true><<<dim3(4, NGRAPH), 256>>>(Hh, alphab, srcb, offb, b1,
                                             nullptr, Ah);
    // layer 2: GEMM -> fp16 Hh
    convT_k<<<(FDIM * FDIM + 255) / 256, 256>>>(W2, Bh, FDIM, FDIM);
    gemm_mma<true><<<dim3(FDIM / 128, NN / 128), 256, GEMM_SMEM>>>(
        Ah, Bh, nullptr, Hh, NN, FDIM, FDIM);
    gat_attn<true><<<NGRAPH, 256>>>(Hh, esrc, edst, ea, a_s2, a_d2, We2, ae2,
                                    alphab, srcb, offb);
    gat_aggr<true><<<dim3(4, NGRAPH), 256>>>(Hh, alphab, srcb, offb, b2,
                                             nullptr, Ah);
    // layer 3: GEMM -> fp16 Hh; aggr -> fp32 bufB (pool/agent input)
    convT_k<<<(FDIM * FDIM + 255) / 256, 256>>>(W3, Bh, FDIM, FDIM);
    gemm_mma<true><<<dim3(FDIM / 128, NN / 128), 256, GEMM_SMEM>>>(
        Ah, Bh, nullptr, Hh, NN, FDIM, FDIM);
    gat_attn<true><<<NGRAPH, 256>>>(Hh, esrc, edst, ea, a_s3, a_d3, We3, ae3,
                                    alphab, srcb, offb);
    gat_aggr<false><<<dim3(4, NGRAPH), 256>>>(Hh, alphab, srcb, offb, b3,
                                              bufB, nullptr);
    // fused pool + agent -> fp16 GRU GEMM operand, then GI GEMM (fp32 out)
    poolagent_k<<<dim3(NGRAPH, FDIM / 128), 128>>>(bufB, Ah);
    convT_k<<<(GRUI * G3 + 255) / 256, 256>>>(Wih, Bh, GRUI, G3);
    gemm_mma<false><<<dim3(G3 / 128, (NGRAPH * NA) / 128), 256, GEMM_SMEM>>>(
        Ah, Bh, GI, nullptr, NGRAPH * NA, G3, GRUI);
    // GRU recurrence (10-launch — frozen)
    cudaMemcpyAsync(h0b, hid0, (size_t)NGRAPH * GRUH * sizeof(float),
                    cudaMemcpyDeviceToDevice);
    for (int t = 0; t < NA; t++) {
        float* hc = (t & 1) ? h1b : h0b;
        float* hn = (t & 1) ? h0b : h1b;
        gru_gh_k<<<NGRAPH / 8, G3>>>(hc, Whh, GHb);
        gru_gate_k<<<NGRAPH, GRUH>>>(GI, t, GHb, hc, bih, bhh, hn, gout,
                                     (t == NA - 1) ? (out + NGRAPH * NA * 3 * 2) : nullptr);
    }
    fc_k<<<NGRAPH * NA, 64>>>(gout, fc1W, fc1b, fc2W, fc2b, logstd, out);
}

// round 16
// speedup vs baseline: 2.0165x; 1.0239x over previous
#include <cuda_runtime.h>
#include <cuda_fp16.h>
#include <cstdint>

#define NODES 50
#define EPG   400
#define NGRAPH 512
#define NN    (NGRAPH*NODES)   // 25600
#define NE    (NGRAPH*EPG)     // 204800
#define FDIM  512
#define HEADS 8
#define CH    64
#define NA    5
#define GRUH  128
#define GRUI  1024
#define G3    384
#define EMAX  456              // padded per-graph edge capacity (450 used)

// ---------------- scratch (static device globals; no allocation) ----------------
__device__ __half g_Hh[NN*FDIM];        // node features (GAT layer input), fp16
__device__ float g_bufB[NN*FDIM];       // layer-3 output fp32 (pool/agent input)
__device__ __half g_Ah[NN*FDIM];        // GEMM A operand
__device__ __half g_Bh[GRUI*G3 > FDIM*FDIM ? GRUI*G3 : FDIM*FDIM];
__device__ float g_alpha[NGRAPH*EMAX*HEADS];
__device__ int   g_srcb[NGRAPH*EMAX];
__device__ int   g_offb[NGRAPH*51];
__device__ float g_GI[NGRAPH*NA*G3];
__device__ float g_GHbuf[NGRAPH*G3];
__device__ float g_h0[NGRAPH*GRUH];
__device__ float g_h1[NGRAPH*GRUH];
__device__ float g_gruout[NGRAPH*NA*GRUH];

// ---------------- helpers ----------------
__device__ __forceinline__ uint32_t smem_u32(const void* p) {
    uint32_t a;
    asm("{ .reg .u64 t; cvta.to.shared.u64 t, %1; cvt.u32.u64 %0, t; }" : "=r"(a) : "l"(p));
    return a;
}
__device__ __forceinline__ void cp16(uint32_t sdst, const void* gsrc) {
    asm volatile("cp.async.cg.shared.global [%0], [%1], 16;" :: "r"(sdst), "l"(gsrc) : "memory");
}
__device__ __forceinline__ void ldsm4(uint32_t& r0, uint32_t& r1, uint32_t& r2,
                                      uint32_t& r3, uint32_t a) {
    asm volatile("ldmatrix.sync.aligned.m8n8.x4.shared.b16 {%0,%1,%2,%3}, [%4];"
                 : "=r"(r0), "=r"(r1), "=r"(r2), "=r"(r3) : "r"(a));
}
__device__ __forceinline__ void mma16816h(float* c, uint32_t a0, uint32_t a1,
                                          uint32_t a2, uint32_t a3,
                                          uint32_t b0, uint32_t b1) {
    asm volatile(
        "mma.sync.aligned.m16n8k16.row.col.f32.f16.f16.f32 "
        "{%0,%1,%2,%3}, {%4,%5,%6,%7}, {%8,%9}, {%0,%1,%2,%3};"
        : "+f"(c[0]), "+f"(c[1]), "+f"(c[2]), "+f"(c[3])
        : "r"(a0), "r"(a1), "r"(a2), "r"(a3), "r"(b0), "r"(b1));
}

// W [K,N] fp32 -> Wt [N,K] fp16 (transposed convert)
__global__ void convT_k(const float* __restrict__ W, __half* __restrict__ hi,
                        int K, int N) {
    int idx = blockIdx.x * 256 + threadIdx.x;
    if (idx >= N * K) return;
    int n = idx / K, k = idx - n * K;
    hi[idx] = __float2half_rn(W[(size_t)k * N + n]);
}

// ---------------- HMMA fp16 GEMM via ldmatrix: C = A[M,K] * B[N,K]^T -------------
#define STAGES 3
#define PITCH 80
#define MAT_BYTES (128*PITCH)
#define STAGE_BYTES (2*MAT_BYTES)        // A | B
#define GEMM_SMEM (STAGES*STAGE_BYTES)   // 61440

template <bool OUTHALF>
__global__ void __launch_bounds__(256) gemm_mma(
    const __half* __restrict__ A, const __half* __restrict__ B,
    float* __restrict__ C, __half* __restrict__ Ch, int M, int N, int K) {
    extern __shared__ char sm8[];
    const uint32_t sb = smem_u32(sm8);
    const int tid = threadIdx.x;
    const int lane = tid & 31, wid = tid >> 5;
    const int wm = wid & 3, wn = wid >> 2;
    const int bm = blockIdx.y * 128, bn = blockIdx.x * 128;
    const int g = lane >> 2, tig = lane & 3;
    const int NCH = K >> 5;

    const char* pA = (const char*)A;
    const char* pB = (const char*)B;
    const size_t rowb = (size_t)K * 2;

    auto load_stage = [&](int kc, int s) {
        uint32_t sbase = sb + s * STAGE_BYTES;
        size_t kb = (size_t)kc * 64;
#pragma unroll
        for (int i = tid; i < 512; i += 256) {
            int r = i >> 2, gg = i & 3;
            uint32_t so = sbase + r * PITCH + gg * 16;
            size_t ga = (size_t)(bm + r) * rowb + kb + gg * 16;
            size_t gb = (size_t)(bn + r) * rowb + kb + gg * 16;
            cp16(so,             pA + ga);
            cp16(so + MAT_BYTES, pB + gb);
        }
        asm volatile("cp.async.commit_group;" ::: "memory");
    };

    float acc[2][8][4];
#pragma unroll
    for (int f = 0; f < 2; f++)
#pragma unroll
        for (int nf = 0; nf < 8; nf++)
#pragma unroll
            for (int c = 0; c < 4; c++) acc[f][nf][c] = 0.f;

    // ldmatrix per-lane address components
    const uint32_t rowA = (uint32_t)(wm * 32 + (lane & 7) + ((lane >> 3) & 1) * 8);
    const uint32_t offA = (uint32_t)((lane >> 4) * 16);
    const uint32_t rowB = (uint32_t)(wn * 64 + ((lane >> 4) & 1) * 8 + (lane & 7));
    const uint32_t offB = (uint32_t)(((lane >> 3) & 1) * 16);

    load_stage(0, 0);
    load_stage(1, 1);

    for (int kc = 0; kc < NCH; kc++) {
        int s = kc % STAGES;
        asm volatile("cp.async.wait_group 1;" ::: "memory");
        __syncthreads();
        if (kc + 2 < NCH) load_stage(kc + 2, (kc + 2) % STAGES);
        else asm volatile("cp.async.commit_group;" ::: "memory");

        uint32_t aA = sb + s * STAGE_BYTES;
        uint32_t aB = aA + MAT_BYTES;
#pragma unroll
        for (int kk = 0; kk < 2; kk++) {
            const uint32_t kbase = kk * 32;
            uint32_t ah[2][4];
#pragma unroll
            for (int f = 0; f < 2; f++) {
                uint32_t addr = aA + (rowA + f * 16) * PITCH + kbase + offA;
                ldsm4(ah[f][0], ah[f][1], ah[f][2], ah[f][3], addr);
            }
#pragma unroll
            for (int p = 0; p < 4; p++) {
                uint32_t b0, b1, b2, b3;   // (b0,b1)=nf 2p, (b2,b3)=nf 2p+1
                uint32_t addr = aB + (rowB + p * 16) * PITCH + kbase + offB;
                ldsm4(b0, b1, b2, b3, addr);
#pragma unroll
                for (int f = 0; f < 2; f++) {
                    mma16816h(acc[f][2*p],   ah[f][0], ah[f][1], ah[f][2], ah[f][3], b0, b1);
                    mma16816h(acc[f][2*p+1], ah[f][0], ah[f][1], ah[f][2], ah[f][3], b2, b3);
                }
            }
        }
        __syncthreads();
    }

#pragma unroll
    for (int f = 0; f < 2; f++) {
        int r0 = bm + wm * 32 + f * 16 + g;
#pragma unroll
        for (int nf = 0; nf < 8; nf++) {
            int c0 = bn + wn * 64 + nf * 8 + 2 * tig;
            if (OUTHALF) {
                *(__half2*)&Ch[(size_t)r0 * N + c0] =
                    __floats2half2_rn(acc[f][nf][0], acc[f][nf][1]);
                *(__half2*)&Ch[(size_t)(r0 + 8) * N + c0] =
                    __floats2half2_rn(acc[f][nf][2], acc[f][nf][3]);
            } else {
                *(float2*)&C[(size_t)r0 * N + c0]       = make_float2(acc[f][nf][0], acc[f][nf][1]);
                *(float2*)&C[(size_t)(r0 + 8) * N + c0] = make_float2(acc[f][nf][2], acc[f][nf][3]);
            }
        }
    }
}

// ---------------- x @ W1  (K=4) -> fp16, 2 features per thread ----------------
__global__ void lin1_k(const float* __restrict__ x, const float* __restrict__ W,
                       __half* __restrict__ out) {
    int idx = blockIdx.x * 256 + threadIdx.x;
    int n = idx >> 8, f = (idx & 255) * 2;
    float4 xv = *(const float4*)(x + (size_t)n * 4);
    float v0 = xv.x*W[f]   + xv.y*W[512+f]   + xv.z*W[1024+f]   + xv.w*W[1536+f];
    float v1 = xv.x*W[f+1] + xv.y*W[512+f+1] + xv.z*W[1024+f+1] + xv.w*W[1536+f+1];
    *(__half2*)&out[(size_t)n * FDIM + f] = __floats2half2_rn(v0, v1);
}

// ---------------- GAT kernel A: attention (fp16 hpre; atomic-free softmax) -------
template <bool LOOPS>
__global__ void __launch_bounds__(256) gat_attn(
    const __half* __restrict__ hpre,
    const int* __restrict__ esrc, const int* __restrict__ edst,
    const float* __restrict__ ea,
    const float* __restrict__ a_src, const float* __restrict__ a_dst,
    const float* __restrict__ We, const float* __restrict__ ae,
    float* __restrict__ galpha, int* __restrict__ gsrcb, int* __restrict__ goffb) {
    __shared__ float sh_ssrc[400];
    __shared__ float sh_sdst[400];
    __shared__ float sh_alS[EMAX*8];
    __shared__ float sh_den[400];
    __shared__ float sh_av[1024];
    __shared__ float sh_weae[8];
    __shared__ float sh_easum[52];
    __shared__ int   sh_srcS[EMAX];
    __shared__ int   sh_dstS[EMAX];
    __shared__ int   sh_cnt[52];
    __shared__ int   sh_off[52];
    __shared__ int   sh_cur[52];

    const int g = blockIdx.x;
    const int nb = g * NODES;
    const int eb = g * EPG;
    const int tid = threadIdx.x;
    const int lane = tid & 31, wid = tid >> 5;
    const int ECNT = LOOPS ? (EPG + NODES) : EPG;

    if (tid < NODES) { sh_cnt[tid] = 0; sh_easum[tid] = 0.f; sh_cur[tid] = 0; }
    for (int i = tid; i < 512; i += 256) {
        sh_av[i] = a_src[i];
        sh_av[512 + i] = a_dst[i];
    }
    if (tid < 8) {
        float s = 0.f;
#pragma unroll
        for (int c = 0; c < 64; c++) s += We[tid * 64 + c] * ae[tid * 64 + c];
        sh_weae[tid] = s;
    }
    __syncthreads();

    for (int e = tid; e < EPG; e += 256) {
        int d = edst[eb + e] - nb;
        atomicAdd(&sh_cnt[d], 1);
        atomicAdd(&sh_easum[d], ea[eb + e]);
    }
    __syncthreads();

    for (int n = wid; n < NODES; n += 8) {
        const uint2* hr = (const uint2*)(hpre + (size_t)(nb + n) * FDIM);
#pragma unroll
        for (int k = 0; k < 4; k++) {
            uint2 u = hr[lane + 32 * k];
            float2 f01 = __half22float2(*(__half2*)&u.x);
            float2 f23 = __half22float2(*(__half2*)&u.y);
            int f = 4 * lane + 128 * k;
            float4 as = *(const float4*)(sh_av + f);
            float4 ad = *(const float4*)(sh_av + 512 + f);
            float s1 = f01.x*as.x + f01.y*as.y + f23.x*as.z + f23.y*as.w;
            float s2 = f01.x*ad.x + f01.y*ad.y + f23.x*ad.z + f23.y*ad.w;
#pragma unroll
            for (int o = 8; o > 0; o >>= 1) {
                s1 += __shfl_xor_sync(0xffffffffu, s1, o);
                s2 += __shfl_xor_sync(0xffffffffu, s2, o);
            }
            if ((lane & 15) == 0) {
                int head = 2 * k + (lane >> 4);
                sh_ssrc[n * 8 + head] = s1;
                sh_sdst[n * 8 + head] = s2;
            }
        }
    }
    __syncthreads();

    if (tid == 0) {
        int o = 0;
        for (int n = 0; n < NODES; n++) { sh_off[n] = o; o += sh_cnt[n] + (LOOPS ? 1 : 0); }
    }
    __syncthreads();

    for (int e = tid; e < ECNT; e += 256) {
        int sl, dl; float eav;
        if (e < EPG) { sl = esrc[eb + e] - nb; dl = edst[eb + e] - nb; eav = ea[eb + e]; }
        else { sl = dl = e - EPG; eav = sh_easum[dl] / fmaxf((float)sh_cnt[dl], 1.f); }
        int pos = sh_off[dl] + atomicAdd(&sh_cur[dl], 1);
        sh_srcS[pos] = sl; sh_dstS[pos] = dl;
#pragma unroll
        for (int h = 0; h < 8; h++) {
            float al = sh_ssrc[sl * 8 + h] + sh_sdst[dl * 8 + h] + eav * sh_weae[h];
            al = al > 0.f ? al : 0.2f * al;
            sh_alS[pos * 8 + h] = al;
        }
    }
    __syncthreads();

    for (int p = tid; p < NODES * HEADS; p += 256) {
        int n = p >> 3, h = p & 7;
        const int beg = sh_off[n], end = beg + (LOOPS ? (sh_cnt[n] + 1) : sh_cnt[n]);
        float m = 0.f;
        for (int j = beg; j < end; j++) m = fmaxf(m, sh_alS[j * 8 + h]);
        float d = 0.f;
        for (int j = beg; j < end; j++) {
            float pv = __expf(sh_alS[j * 8 + h] - m);
            sh_alS[j * 8 + h] = pv;
            d += pv;
        }
        sh_den[p] = 1.f / (d + 1e-16f);
    }
    __syncthreads();

    float* ga = galpha + (size_t)g * EMAX * 8;
    int* gs = gsrcb + (size_t)g * EMAX;
    for (int i = tid; i < ECNT; i += 256) {
        int dl = sh_dstS[i];
        float4 o0, o1;
        o0.x = sh_alS[i*8+0] * sh_den[dl*8+0];
        o0.y = sh_alS[i*8+1] * sh_den[dl*8+1];
        o0.z = sh_alS[i*8+2] * sh_den[dl*8+2];
        o0.w = sh_alS[i*8+3] * sh_den[dl*8+3];
        o1.x = sh_alS[i*8+4] * sh_den[dl*8+4];
        o1.y = sh_alS[i*8+5] * sh_den[dl*8+5];
        o1.z = sh_alS[i*8+6] * sh_den[dl*8+6];
        o1.w = sh_alS[i*8+7] * sh_den[dl*8+7];
        ((float4*)(ga + i * 8))[0] = o0;
        ((float4*)(ga + i * 8))[1] = o1;
        gs[i] = sh_srcS[i];
    }
    if (tid < NODES) goffb[g * 51 + tid] = sh_off[tid];
    if (tid == NODES) goffb[g * 51 + NODES] = ECNT;
}

// ---------------- GAT kernel B: aggregation (fp16 hpre; x4-vectorized) -----------
template <bool OUTFP16>
__global__ void __launch_bounds__(256) gat_aggr(
    const __half* __restrict__ hpre,
    const float* __restrict__ galpha, const int* __restrict__ gsrcb,
    const int* __restrict__ goffb,
    const float* __restrict__ bias, float* __restrict__ xout,
    __half* __restrict__ outh) {
    __shared__ float sh_hs[NODES * 128];
    __shared__ float sh_al[EMAX * 2];
    __shared__ int   sh_src[EMAX];
    __shared__ int   sh_off[51];

    const int sl = blockIdx.x;
    const int g = blockIdx.y;
    const int nb = g * NODES;
    const int tid = threadIdx.x;
    const int lane = tid & 31, wg = tid >> 5;
    const int ECNT = goffb[g * 51 + NODES];

    for (int i = tid; i < NODES * 64; i += 256) {
        int n = i >> 6, ff2 = i & 63;
        __half2 v = *(const __half2*)(hpre + (size_t)(nb + n) * FDIM + sl * 128 + ff2 * 2);
        float2 f = __half22float2(v);
        sh_hs[n * 128 + ff2 * 2]     = f.x;
        sh_hs[n * 128 + ff2 * 2 + 1] = f.y;
    }
    const float* ga = galpha + (size_t)g * EMAX * 8 + sl * 2;
    const int* gs = gsrcb + (size_t)g * EMAX;
    for (int i = tid; i < ECNT; i += 256) {
        sh_al[i * 2]     = ga[i * 8];
        sh_al[i * 2 + 1] = ga[i * 8 + 1];
        sh_src[i] = gs[i];
    }
    if (tid <= NODES) sh_off[tid] = goffb[g * 51 + tid];
    __syncthreads();

    const int hsel = lane >> 4;
    const int f0 = lane * 4;
    const float4 bv = *(const float4*)(bias + sl * 128 + f0);
    for (int n = wg; n < NODES; n += 8) {
        float4 acc = {0.f, 0.f, 0.f, 0.f};
        const int beg = sh_off[n], end = sh_off[n + 1];
        for (int j = beg; j < end; j++) {
            const int s = sh_src[j];
            const float a = sh_al[j * 2 + hsel];
            const float4 h = *(const float4*)(sh_hs + s * 128 + f0);
            acc.x += a * h.x; acc.y += a * h.y;
            acc.z += a * h.z; acc.w += a * h.w;
        }
        float4 v;
        v.x = fmaxf(acc.x + bv.x, 0.f);
        v.y = fmaxf(acc.y + bv.y, 0.f);
        v.z = fmaxf(acc.z + bv.z, 0.f);
        v.w = fmaxf(acc.w + bv.w, 0.f);
        size_t idx = (size_t)(nb + n) * FDIM + sl * 128 + f0;
        if (OUTFP16) {
            __half2* op = (__half2*)(outh + idx);
            op[0] = __floats2half2_rn(v.x, v.y);
            op[1] = __floats2half2_rn(v.z, v.w);
        } else {
            *(float4*)(xout + idx) = v;
        }
    }
}

// ---------------- fused pool + agent rows -> fp16 GRU GEMM operand ---------------
__global__ void poolagent_k(const float* __restrict__ x3, __half* __restrict__ Ah) {
    int b = blockIdx.x;
    int f = blockIdx.y * 128 + threadIdx.x;
    float s = 0.f;
#pragma unroll 10
    for (int n = 0; n < NODES; n++) {
        float v = x3[(size_t)(b * NODES + n) * FDIM + f];
        s += v;
        if (n < NA)
            Ah[(size_t)(b * NA + n) * GRUI + f] = __float2half_rn(v);
    }
    __half h = __float2half_rn(s * (1.f / 50.f));
#pragma unroll
    for (int t = 0; t < NA; t++)
        Ah[(size_t)(b * NA + t) * GRUI + 512 + f] = h;
}

// ---------------- GRU: GH = h @ Whh ----------------
__global__ void gru_gh_k(const float* __restrict__ h, const float* __restrict__ Whh,
                         float* __restrict__ GH) {
    __shared__ float hs[8 * GRUH];
    int b0 = blockIdx.x * 8;
    int tid = threadIdx.x;
    for (int i = tid; i < 8 * GRUH; i += 384) hs[i] = h[b0 * GRUH + i];
    __syncthreads();
    float acc[8];
#pragma unroll
    for (int r = 0; r < 8; r++) acc[r] = 0.f;
    for (int k = 0; k < GRUH; k++) {
        float w = Whh[k * G3 + tid];
#pragma unroll
        for (int r = 0; r < 8; r++) acc[r] += hs[r * GRUH + k] * w;
    }
#pragma unroll
    for (int r = 0; r < 8; r++) GH[(b0 + r) * G3 + tid] = acc[r];
}

// ---------------- GRU gate math ----------------
__global__ void gru_gate_k(const float* __restrict__ GI, int t,
                           const float* __restrict__ GHb, const float* __restrict__ hprev,
                           const float* __restrict__ bih, const float* __restrict__ bhh,
                           float* __restrict__ hnew, float* __restrict__ gout,
                           float* __restrict__ hlast) {
    int b = blockIdx.x, j = threadIdx.x;
    const float* gi = GI + (size_t)(b * NA + t) * G3;
    const float* gh = GHb + (size_t)b * G3;
    float ir = gi[j] + bih[j];
    float iz = gi[j + 128] + bih[j + 128];
    float in_ = gi[j + 256] + bih[j + 256];
    float hr = gh[j] + bhh[j];
    float hz = gh[j + 128] + bhh[j + 128];
    float hn = gh[j + 256] + bhh[j + 256];
    float r = 1.f / (1.f + expf(-(ir + hr)));
    float z = 1.f / (1.f + expf(-(iz + hz)));
    float nn = tanhf(in_ + r * hn);
    float hp = hprev[b * GRUH + j];
    float h = (1.f - z) * nn + z * hp;
    hnew[b * GRUH + j] = h;
    gout[(size_t)(b * NA + t) * GRUH + j] = h;
    if (hlast) hlast[b * GRUH + j] = h;
}

// ---------------- FC head ----------------
__global__ void fc_k(const float* __restrict__ gout, const float* __restrict__ W1,
                     const float* __restrict__ b1, const float* __restrict__ W2,
                     const float* __restrict__ b2, const float* __restrict__ ls,
                     float* __restrict__ out) {
    __shared__ float g[128];
    __shared__ float f1[64];
    int r = blockIdx.x, tid = threadIdx.x;
    g[tid] = gout[(size_t)r * GRUH + tid];
    g[tid + 64] = gout[(size_t)r * GRUH + tid + 64];
    __syncthreads();
    float acc = b1[tid];
#pragma unroll 8
    for (int k = 0; k < 128; k++) acc += g[k] * W1[k * 64 + tid];
    f1[tid] = acc > 0.f ? acc : 0.f;
    __syncthreads();
    if (tid < 3) {
        float a2 = b2[tid];
#pragma unroll
        for (int k = 0; k < 64; k++) a2 += f1[k] * W2[k * 3 + tid];
        out[r * 3 + tid] = a2;
        float l = ls[tid];
        l = fminf(fmaxf(l, -20.f), 2.f);
        out[NGRAPH * NA * 3 + r * 3 + tid] = expf(l);
    }
}

// ---------------- launch ----------------
extern "C" void kernel_launch(void* const* d_in, const int* in_sizes, int n_in,
                              void* d_out, int out_size) {
    const float* x      = (const float*)d_in[0];
    const int*   ei     = (const int*)d_in[1];
    const float* ea     = (const float*)d_in[2];
    const float* hid0   = (const float*)d_in[3];
    const float* W1     = (const float*)d_in[4];
    const float* a_s1   = (const float*)d_in[5];
    const float* a_d1   = (const float*)d_in[6];
    const float* We1    = (const float*)d_in[7];
    const float* ae1    = (const float*)d_in[8];
    const float* b1     = (const float*)d_in[9];
    const float* W2     = (const float*)d_in[10];
    const float* a_s2   = (const float*)d_in[11];
    const float* a_d2   = (const float*)d_in[12];
    const float* We2    = (const float*)d_in[13];
    const float* ae2    = (const float*)d_in[14];
    const float* b2     = (const float*)d_in[15];
    const float* W3     = (const float*)d_in[16];
    const float* a_s3   = (const float*)d_in[17];
    const float* a_d3   = (const float*)d_in[18];
    const float* We3    = (const float*)d_in[19];
    const float* ae3    = (const float*)d_in[20];
    const float* b3     = (const float*)d_in[21];
    const float* Wih    = (const float*)d_in[22];
    const float* Whh    = (const float*)d_in[23];
    const float* bih    = (const float*)d_in[24];
    const float* bhh    = (const float*)d_in[25];
    const float* fc1W   = (const float*)d_in[26];
    const float* fc1b   = (const float*)d_in[27];
    const float* fc2W   = (const float*)d_in[28];
    const float* fc2b   = (const float*)d_in[29];
    const float* logstd = (const float*)d_in[30];
    float* out = (float*)d_out;

    float *bufB, *GI, *GHb, *h0b, *h1b, *gout, *alphab;
    int *srcb, *offb;
    __half *Hh, *Ah, *Bh;
    cudaGetSymbolAddress((void**)&Hh,   g_Hh);
    cudaGetSymbolAddress((void**)&bufB, g_bufB);
    cudaGetSymbolAddress((void**)&GI,   g_GI);
    cudaGetSymbolAddress((void**)&GHb,  g_GHbuf);
    cudaGetSymbolAddress((void**)&h0b,  g_h0);
    cudaGetSymbolAddress((void**)&h1b,  g_h1);
    cudaGetSymbolAddress((void**)&gout, g_gruout);
    cudaGetSymbolAddress((void**)&alphab, g_alpha);
    cudaGetSymbolAddress((void**)&srcb, g_srcb);
    cudaGetSymbolAddress((void**)&offb, g_offb);
    cudaGetSymbolAddress((void**)&Ah, g_Ah);
    cudaGetSymbolAddress((void**)&Bh, g_Bh);

    cudaFuncSetAttribute((const void*)gemm_mma<false>,
                         cudaFuncAttributeMaxDynamicSharedMemorySize, GEMM_SMEM);
    cudaFuncSetAttribute((const void*)gemm_mma<true>,
                         cudaFuncAttributeMaxDynamicSharedMemorySize, GEMM_SMEM);

    const int* esrc = ei;
    const int* edst = ei + NE;

    // layer 1
    lin1_k<<<NN, 256>>>(x, W1, Hh);
    gat_attn<false><<<NGRAPH, 256>>>(Hh, esrc, edst, ea, a_s1, a_d1, We1, ae1,
                                     alphab, srcb, offb);
    gat_aggr<true><<<dim3(4, NGRAPH), 256>>>(Hh, alphab, srcb, offb, b1,
                                             nullptr, Ah);
    // layer 2
    convT_k<<<(FDIM * FDIM + 255) / 256, 256>>>(W2, Bh, FDIM, FDIM);
    gemm_mma<true><<<dim3(FDIM / 128, NN / 128), 256, GEMM_SMEM>>>(
        Ah, Bh, nullptr, Hh, NN, FDIM, FDIM);
    gat_attn<true><<<NGRAPH, 256>>>(Hh, esrc, edst, ea, a_s2, a_d2, We2, ae2,
                                    alphab, srcb, offb);
    gat_aggr<true><<<dim3(4, NGRAPH), 256>>>(Hh, alphab, srcb, offb, b2,
                                             nullptr, Ah);
    // layer 3
    convT_k<<<(FDIM * FDIM + 255) / 256, 256>>>(W3, Bh, FDIM, FDIM);
    gemm_mma<true><<<dim3(FDIM / 128, NN / 128), 256, GEMM_SMEM>>>(
        Ah, Bh, nullptr, Hh, NN, FDIM, FDIM);
    gat_attn<true><<<NGRAPH, 256>>>(Hh, esrc, edst, ea, a_s3, a_d3, We3, ae3,
                                    alphab, srcb, offb);
    gat_aggr<false><<<dim3(4, NGRAPH), 256>>>(Hh, alphab, srcb, offb, b3,
                                              bufB, nullptr);
    // fused pool + agent -> fp16 GRU GEMM operand, then GI GEMM
    poolagent_k<<<dim3(NGRAPH, FDIM / 128), 128>>>(bufB, Ah);
    convT_k<<<(GRUI * G3 + 255) / 256, 256>>>(Wih, Bh, GRUI, G3);
    gemm_mma<false><<<dim3(G3 / 128, (NGRAPH * NA) / 128), 256, GEMM_SMEM>>>(
        Ah, Bh, GI, nullptr, NGRAPH * NA, G3, GRUI);
    // GRU recurrence (10-launch — frozen)
    cudaMemcpyAsync(h0b, hid0, (size_t)NGRAPH * GRUH * sizeof(float),
                    cudaMemcpyDeviceToDevice);
    for (int t = 0; t < NA; t++) {
        float* hc = (t & 1) ? h1b : h0b;
        float* hn = (t & 1) ? h0b : h1b;
        gru_gh_k<<<NGRAPH / 8, G3>>>(hc, Whh, GHb);
        gru_gate_k<<<NGRAPH, GRUH>>>(GI, t, GHb, hc, bih, bhh, hn, gout,
                                     (t == NA - 1) ? (out + NGRAPH * NA * 3 * 2) : nullptr);
    }
    fc_k<<<NGRAPH * NA, 64>>>(gout, fc1W, fc1b, fc2W, fc2b, logstd, out);
}